// round 11
// baseline (speedup 1.0000x reference)
#include <cuda_runtime.h>
#include <math.h>
#include <stdint.h>

#define BMAX 65536

// ---- scratch (allocation-free rule: __device__ globals) ----
__device__ __align__(16) float g_bufA[(size_t)BMAX * 17 * 64];
__device__ __align__(16) float g_bufB[(size_t)BMAX * 17 * 64];
__device__ __align__(16) float g_z[(size_t)BMAX * 256];
__device__ __align__(16) float g_wp1t[256 * 1088];   // W_p1^T (n-major), tf32 RNA-rounded
__device__ __align__(16) float g_wgt1[64 * 64];      // W_gc1^T (n-major), tf32
__device__ __align__(16) float g_wgt2[64 * 64];      // W_gc2^T (n-major), tf32
__device__ double g_stats[68];
__device__ float g_scale1[17], g_shift1[17], g_scale2[17], g_shift2[17];

// ---- adjacency tables (I + A_norm) ----
__constant__ int   c_cnt[17] = {2,0,0,0,0,4,4,2,2,1,1,3,3,2,2,1,1};
__constant__ float c_w[17]   = {0.5f,0.f,0.f,0.f,0.f,0.25f,0.25f,0.5f,0.5f,1.f,1.f,
                                (1.f/3.f),(1.f/3.f),0.5f,0.5f,1.f,1.f};
__constant__ int   c_nb[17][4] = {
    {5,6,0,0},  {0,0,0,0}, {0,0,0,0}, {0,0,0,0}, {0,0,0,0},
    {7,6,11,0}, {8,5,12,0},
    {5,9,0,0},  {6,10,0,0},
    {7,0,0,0},  {8,0,0,0},
    {5,12,13,0},{6,11,14,0},
    {11,15,0,0},{12,16,0,0},
    {13,0,0,0}, {14,0,0,0}
};

// ---- helpers ----
typedef unsigned long long ull;
__device__ __forceinline__ ull pack2(float x, float y) {
    ull r; asm("mov.b64 %0, {%1,%2};" : "=l"(r) : "f"(x), "f"(y)); return r;
}
__device__ __forceinline__ void unpack2(ull v, float &x, float &y) {
    asm("mov.b64 {%0,%1}, %2;" : "=f"(x), "=f"(y) : "l"(v));
}
__device__ __forceinline__ void fma2(ull &d, ull a, ull b) {
    asm("fma.rn.f32x2 %0, %1, %2, %3;" : "=l"(d) : "l"(a), "l"(b), "l"(d));
}
__device__ __forceinline__ float rna_tf32(float v) {
    asm("cvt.rna.tf32.f32 %0, %1;" : "=f"(v) : "f"(v));
    return v;
}
__device__ __forceinline__ uint32_t s2u(const void* p) {
    uint32_t a;
    asm("{ .reg .u64 t; cvta.to.shared.u64 t, %1; cvt.u32.u64 %0, t; }" : "=r"(a) : "l"(p));
    return a;
}
#define MMA_TF32(acc, a0, a1, a2, a3, b0, b1) \
    asm volatile( \
        "mma.sync.aligned.m16n8k8.row.col.f32.tf32.tf32.f32 " \
        "{%0,%1,%2,%3}, {%4,%5,%6,%7}, {%8,%9}, {%0,%1,%2,%3};" \
        : "+f"(acc[0]), "+f"(acc[1]), "+f"(acc[2]), "+f"(acc[3]) \
        : "r"(a0), "r"(a1), "r"(a2), "r"(a3), "r"(b0), "r"(b1))

__global__ void k_zero() {
    if (threadIdx.x < 68) g_stats[threadIdx.x] = 0.0;
}

// ---- transpose W_p1 (1088x256) -> g_wp1t (256x1088), tf32 RNA-rounded ----
__global__ void __launch_bounds__(256)
k_tr(const float* __restrict__ W, float* __restrict__ T) {
    int i = blockIdx.x * 256 + threadIdx.x;
    if (i >= 1088 * 256) return;
    int k = i >> 8, n = i & 255;
    T[(size_t)n * 1088 + k] = rna_tf32(W[i]);
}

// ---- transpose W_gc (64x64) -> (n-major 64x64), tf32 RNA-rounded ----
__global__ void __launch_bounds__(256)
k_trg(const float* __restrict__ W, float* __restrict__ T) {
    int i = blockIdx.x * 256 + threadIdx.x;
    if (i >= 4096) return;
    int k = i >> 6, n = i & 63;
    T[n * 64 + k] = rna_tf32(W[i]);
}

// ---- stats-only pass: (optional encoder) + aggregation -> per-node sum/sumsq ----
// ENC=1: src=x (B,17,2); ENC=0: src=h (B,17,64). NO writes of y.
template <int ENC>
__global__ void __launch_bounds__(256)
k_stats(const float* __restrict__ src, const float* __restrict__ W,
        const float* __restrict__ bvec, int B, int set) {
    __shared__ float h_sm[8 * 1156];
    __shared__ float ss[17], qq[17];
    int tid = threadIdx.x;
    int s0 = blockIdx.x * 8;
    if (tid < 17) { ss[tid] = 0.f; qq[tid] = 0.f; }

    for (int idx = tid; idx < 272; idx += 256) {
        int n = idx >> 4, c4 = idx & 15;
        float4 w0, w1, bb;
        if (ENC) {
            w0 = *(const float4*)(W + c4 * 4);
            w1 = *(const float4*)(W + 64 + c4 * 4);
            bb = *(const float4*)(bvec + c4 * 4);
        }
#pragma unroll
        for (int s = 0; s < 8; s++) {
            int e = s0 + s;
            if (e >= B) break;
            float4 v;
            if (ENC) {
                float x0 = src[((size_t)e * 17 + n) * 2];
                float x1 = src[((size_t)e * 17 + n) * 2 + 1];
                v.x = fmaxf(fmaf(x0, w0.x, fmaf(x1, w1.x, bb.x)), 0.f);
                v.y = fmaxf(fmaf(x0, w0.y, fmaf(x1, w1.y, bb.y)), 0.f);
                v.z = fmaxf(fmaf(x0, w0.z, fmaf(x1, w1.z, bb.z)), 0.f);
                v.w = fmaxf(fmaf(x0, w0.w, fmaf(x1, w1.w, bb.w)), 0.f);
            } else {
                v = *(const float4*)(src + ((size_t)e * 17 + n) * 64 + c4 * 4);
            }
            *(float4*)&h_sm[s * 1156 + n * 68 + c4 * 4] = v;
        }
    }
    __syncthreads();

    for (int idx = tid; idx < 272; idx += 256) {
        int n = idx >> 4, c4 = idx & 15;
        float w = c_w[n];
        int cnt = c_cnt[n];
        float sp = 0.f, qp = 0.f;
#pragma unroll
        for (int s = 0; s < 8; s++) {
            int e = s0 + s;
            if (e >= B) break;
            float4 acc = *(const float4*)&h_sm[s * 1156 + n * 68 + c4 * 4];
            for (int j = 0; j < cnt; j++) {
                const float4 hb = *(const float4*)&h_sm[s * 1156 + c_nb[n][j] * 68 + c4 * 4];
                acc.x = fmaf(w, hb.x, acc.x);
                acc.y = fmaf(w, hb.y, acc.y);
                acc.z = fmaf(w, hb.z, acc.z);
                acc.w = fmaf(w, hb.w, acc.w);
            }
            sp += acc.x + acc.y + acc.z + acc.w;
            qp = fmaf(acc.x, acc.x, fmaf(acc.y, acc.y, fmaf(acc.z, acc.z, fmaf(acc.w, acc.w, qp))));
        }
        atomicAdd(&ss[n], sp);
        atomicAdd(&qq[n], qp);
    }
    __syncthreads();
    if (tid < 17) {
        atomicAdd(&g_stats[set * 34 + 2 * tid], (double)ss[tid]);
        atomicAdd(&g_stats[set * 34 + 2 * tid + 1], (double)qq[tid]);
    }
}

// ---- finalize BN stats -> fused scale/shift ----
__global__ void k_fin(const float* __restrict__ gamma, const float* __restrict__ beta,
                      double invN, int set) {
    int i = threadIdx.x;
    if (i >= 17) return;
    double s = g_stats[set * 34 + 2 * i];
    double q = g_stats[set * 34 + 2 * i + 1];
    double mean = s * invN;
    double var = q * invN - mean * mean;
    if (var < 0.0) var = 0.0;
    float inv = (float)(1.0 / sqrt(var + 1e-5));
    float sc = gamma[i] * inv;
    float sh = beta[i] - (float)mean * sc;
    if (set == 0) { g_scale1[i] = sc; g_shift1[i] = sh; }
    else          { g_scale2[i] = sc; g_shift2[i] = sh; }
}

// ---- fused gc layer via tf32 mma ----
// LAYER=1: src=x, h=relu(enc(x)); LAYER=2: src=h2 (M17,64).
// In-kernel: y = h + agg(h) (halo staging of whole samples), affine(BN), tf32,
// then C = relu(y' @ W + bias). RND on LAYER=2 output (feeds p1 mma).
// smem: hs[153][68] staging + As[128][68] + Ws[64][68].
#define GCF_HS   (153 * 68)
#define GCF_AS   (128 * 68)
#define GCF_WS   (64 * 68)
#define GCF_SMEM ((GCF_HS + GCF_AS + GCF_WS) * 4)
template <int LAYER>
__global__ void __launch_bounds__(256)
k_gcf(const float* __restrict__ src, const float* __restrict__ Wenc,
      const float* __restrict__ benc, const float* __restrict__ Wt,
      const float* __restrict__ bias, float* __restrict__ C, int M17) {
    extern __shared__ float smf[];
    float* hs = smf;
    float* As = smf + GCF_HS;
    float* Ws = As + GCF_AS;
    const int tid = threadIdx.x;
    const int w = tid >> 5, lane = tid & 31;
    const int gid = lane >> 2, tig = lane & 3;
    const size_t m0 = (size_t)blockIdx.x * 128;
    const int wm = (w >> 1) * 32, wn = (w & 1) * 32;

    // halo range: whole samples covering [m0, m0+128)
    const int R0 = ((int)(m0 / 17)) * 17;
    int R1 = ((int)(m0 + 128 + 16) / 17) * 17;
    if (R1 > M17) R1 = M17;
    const int nrows = R1 - R0;          // <= 153

    // stage h for all halo rows
    for (int idx = tid; idx < nrows * 16; idx += 256) {
        int row = idx >> 4, c4 = idx & 15;
        float4 v;
        if (LAYER == 1) {
            int g = R0 + row;
            float x0 = __ldg(src + (size_t)g * 2);
            float x1 = __ldg(src + (size_t)g * 2 + 1);
            float4 w0 = *(const float4*)(Wenc + c4 * 4);
            float4 w1 = *(const float4*)(Wenc + 64 + c4 * 4);
            float4 bb = *(const float4*)(benc + c4 * 4);
            v.x = fmaxf(fmaf(x0, w0.x, fmaf(x1, w1.x, bb.x)), 0.f);
            v.y = fmaxf(fmaf(x0, w0.y, fmaf(x1, w1.y, bb.y)), 0.f);
            v.z = fmaxf(fmaf(x0, w0.z, fmaf(x1, w1.z, bb.z)), 0.f);
            v.w = fmaxf(fmaf(x0, w0.w, fmaf(x1, w1.w, bb.w)), 0.f);
        } else {
            v = *(const float4*)(src + (size_t)(R0 + row) * 64 + c4 * 4);
        }
        *(float4*)&hs[row * 68 + c4 * 4] = v;
    }
    // load Wt (already tf32)
    for (int idx = tid; idx < 64 * 16; idx += 256) {
        int row = idx >> 4, seg = idx & 15;
        *(float4*)&Ws[row * 68 + seg * 4] = *(const float4*)(Wt + row * 64 + seg * 4);
    }
    __syncthreads();

    // y = h + agg(h), affine, tf32 -> As (target rows only)
    const int off = (int)(m0 - R0);
    for (int idx = tid; idx < 128 * 16; idx += 256) {
        int row = idx >> 4, c4 = idx & 15;
        int lr = off + row;
        int sm = lr / 17, nd = lr - sm * 17;
        float4 acc = *(const float4*)&hs[lr * 68 + c4 * 4];
        float ww = c_w[nd];
        int cnt = c_cnt[nd];
        for (int j = 0; j < cnt; j++) {
            const float4 hb = *(const float4*)&hs[(sm * 17 + c_nb[nd][j]) * 68 + c4 * 4];
            acc.x = fmaf(ww, hb.x, acc.x);
            acc.y = fmaf(ww, hb.y, acc.y);
            acc.z = fmaf(ww, hb.z, acc.z);
            acc.w = fmaf(ww, hb.w, acc.w);
        }
        float sc = (LAYER == 1) ? g_scale1[nd] : g_scale2[nd];
        float sh = (LAYER == 1) ? g_shift1[nd] : g_shift2[nd];
        float* ap = &As[row * 68 + c4 * 4];
        ap[0] = rna_tf32(fmaf(acc.x, sc, sh));
        ap[1] = rna_tf32(fmaf(acc.y, sc, sh));
        ap[2] = rna_tf32(fmaf(acc.z, sc, sh));
        ap[3] = rna_tf32(fmaf(acc.w, sc, sh));
    }
    __syncthreads();

    float acc[2][4][4];
#pragma unroll
    for (int mi = 0; mi < 2; mi++)
#pragma unroll
        for (int ni = 0; ni < 4; ni++)
#pragma unroll
            for (int r = 0; r < 4; r++) acc[mi][ni][r] = 0.f;

#pragma unroll
    for (int ks = 0; ks < 8; ks++) {
        uint32_t af[2][4], bf[4][2];
#pragma unroll
        for (int mi = 0; mi < 2; mi++) {
            int rm = wm + mi * 16 + gid;
            af[mi][0] = __float_as_uint(As[rm * 68 + ks * 8 + tig]);
            af[mi][1] = __float_as_uint(As[(rm + 8) * 68 + ks * 8 + tig]);
            af[mi][2] = __float_as_uint(As[rm * 68 + ks * 8 + tig + 4]);
            af[mi][3] = __float_as_uint(As[(rm + 8) * 68 + ks * 8 + tig + 4]);
        }
#pragma unroll
        for (int ni = 0; ni < 4; ni++) {
            int rn = wn + ni * 8 + gid;
            bf[ni][0] = __float_as_uint(Ws[rn * 68 + ks * 8 + tig]);
            bf[ni][1] = __float_as_uint(Ws[rn * 68 + ks * 8 + tig + 4]);
        }
#pragma unroll
        for (int mi = 0; mi < 2; mi++)
#pragma unroll
            for (int ni = 0; ni < 4; ni++)
                MMA_TF32(acc[mi][ni], af[mi][0], af[mi][1], af[mi][2], af[mi][3],
                         bf[ni][0], bf[ni][1]);
    }

#pragma unroll
    for (int mi = 0; mi < 2; mi++) {
        size_t row = m0 + wm + mi * 16 + gid;
#pragma unroll
        for (int ni = 0; ni < 4; ni++) {
            int col = wn + ni * 8 + tig * 2;
            float b0 = __ldg(bias + col), b1 = __ldg(bias + col + 1);
            float2 v0, v1;
            v0.x = fmaxf(acc[mi][ni][0] + b0, 0.f);
            v0.y = fmaxf(acc[mi][ni][1] + b1, 0.f);
            v1.x = fmaxf(acc[mi][ni][2] + b0, 0.f);
            v1.y = fmaxf(acc[mi][ni][3] + b1, 0.f);
            if (LAYER == 2) {
                v0.x = rna_tf32(v0.x); v0.y = rna_tf32(v0.y);
                v1.x = rna_tf32(v1.x); v1.y = rna_tf32(v1.y);
            }
            *(float2*)(C + row * 64 + col) = v0;
            *(float2*)(C + (row + 8) * 64 + col) = v1;
        }
    }
}

// ---- p1 via warp-level tf32 mma: g_z = relu(A(B,1088) @ Wp1 + b_p1) ----
// grid = (2, B/128): x = N-half (L2 reuse of A between the pair), y = M-tile.
#define P1_STAGE_F (128 * 36)
#define P1_SMEM (2 * 2 * P1_STAGE_F * 4)
__global__ void __launch_bounds__(256)
k_p1mma(const float* __restrict__ A, const float* __restrict__ Bt,
        const float* __restrict__ bias, float* __restrict__ C, int B) {
    extern __shared__ float smf[];
    const uint32_t sb = s2u(smf);
    const int tid = threadIdx.x;
    const int w = tid >> 5, lane = tid & 31;
    const int gid = lane >> 2, tig = lane & 3;
    const size_t m0 = (size_t)blockIdx.y * 128;
    const int n0 = blockIdx.x * 128;
    const int wm = (w >> 2) * 64, wn = (w & 3) * 32;

    float acc[4][4][4];
#pragma unroll
    for (int mi = 0; mi < 4; mi++)
#pragma unroll
        for (int ni = 0; ni < 4; ni++)
#pragma unroll
            for (int r = 0; r < 4; r++) acc[mi][ni][r] = 0.f;

    auto load_chunk = [&](int c, int s) {
        uint32_t base = sb + (uint32_t)(s * 2 * P1_STAGE_F) * 4;
        int kc = c * 32;
#pragma unroll
        for (int j = 0; j < 4; j++) {
            int u = tid + j * 256;
            int row = u >> 3, seg = u & 7;
            const float* src = A + (m0 + row) * 1088 + kc + seg * 4;
            uint32_t d = base + (uint32_t)(row * 36 + seg * 4) * 4;
            asm volatile("cp.async.cg.shared.global [%0], [%1], 16;" :: "r"(d), "l"(src) : "memory");
        }
#pragma unroll
        for (int j = 0; j < 4; j++) {
            int u = tid + j * 256;
            int row = u >> 3, seg = u & 7;
            const float* src = Bt + (size_t)(n0 + row) * 1088 + kc + seg * 4;
            uint32_t d = base + (uint32_t)(P1_STAGE_F + row * 36 + seg * 4) * 4;
            asm volatile("cp.async.cg.shared.global [%0], [%1], 16;" :: "r"(d), "l"(src) : "memory");
        }
        asm volatile("cp.async.commit_group;" ::: "memory");
    };

    load_chunk(0, 0);
    load_chunk(1, 1);

    for (int c = 0; c < 34; c++) {
        int s = c & 1;
        if (c == 33) asm volatile("cp.async.wait_group 0;" ::: "memory");
        else         asm volatile("cp.async.wait_group 1;" ::: "memory");
        __syncthreads();
        const float* As_s = smf + s * 2 * P1_STAGE_F;
        const float* Bs_s = As_s + P1_STAGE_F;
#pragma unroll
        for (int ks = 0; ks < 4; ks++) {
            uint32_t af[4][4], bf[4][2];
#pragma unroll
            for (int mi = 0; mi < 4; mi++) {
                int rm = wm + mi * 16 + gid;
                af[mi][0] = __float_as_uint(As_s[rm * 36 + ks * 8 + tig]);
                af[mi][1] = __float_as_uint(As_s[(rm + 8) * 36 + ks * 8 + tig]);
                af[mi][2] = __float_as_uint(As_s[rm * 36 + ks * 8 + tig + 4]);
                af[mi][3] = __float_as_uint(As_s[(rm + 8) * 36 + ks * 8 + tig + 4]);
            }
#pragma unroll
            for (int ni = 0; ni < 4; ni++) {
                int rn = wn + ni * 8 + gid;
                bf[ni][0] = __float_as_uint(Bs_s[rn * 36 + ks * 8 + tig]);
                bf[ni][1] = __float_as_uint(Bs_s[rn * 36 + ks * 8 + tig + 4]);
            }
#pragma unroll
            for (int mi = 0; mi < 4; mi++)
#pragma unroll
                for (int ni = 0; ni < 4; ni++)
                    MMA_TF32(acc[mi][ni], af[mi][0], af[mi][1], af[mi][2], af[mi][3],
                             bf[ni][0], bf[ni][1]);
        }
        __syncthreads();
        if (c + 2 < 34) load_chunk(c + 2, s);
    }

#pragma unroll
    for (int mi = 0; mi < 4; mi++) {
        size_t row = m0 + wm + mi * 16 + gid;
#pragma unroll
        for (int ni = 0; ni < 4; ni++) {
            int col = n0 + wn + ni * 8 + tig * 2;
            float b0 = __ldg(bias + col), b1 = __ldg(bias + col + 1);
            float2 v0, v1;
            v0.x = fmaxf(acc[mi][ni][0] + b0, 0.f);
            v0.y = fmaxf(acc[mi][ni][1] + b1, 0.f);
            v1.x = fmaxf(acc[mi][ni][2] + b0, 0.f);
            v1.y = fmaxf(acc[mi][ni][3] + b1, 0.f);
            *(float2*)(C + row * 256 + col) = v0;
            *(float2*)(C + (row + 8) * 256 + col) = v1;
        }
    }
}

// ---- f32x2 GEMM, BN=128 (p2): thread tile 8x8, BK=16, fused L2 norm ----
template <int RELU, int NORM>
__global__ void __launch_bounds__(256)
k_gemm128(const float* __restrict__ A, const float* __restrict__ W,
          const float* __restrict__ bias, float* __restrict__ C,
          int M, int N, int K) {
    __shared__ float As[16 * 130];
    __shared__ float Bs[16 * 256];
    int tid = threadIdx.x;
    int tx = tid & 15, ty = tid >> 4;
    size_t m0 = (size_t)blockIdx.x * 128;
    int n0 = blockIdx.y * 128;

    ull acc[4][8];
#pragma unroll
    for (int j = 0; j < 8; j++) {
        float bv = bias[n0 + tx + 16 * j];
        ull pk = pack2(bv, bv);
#pragma unroll
        for (int p = 0; p < 4; p++) acc[p][j] = pk;
    }

    for (int kc = 0; kc < K; kc += 16) {
#pragma unroll
        for (int i = 0; i < 2; i++) {
            int t4 = tid + i * 256;
            int row = t4 >> 2, k4 = t4 & 3;
            float4 v = *(const float4*)(A + (m0 + row) * K + kc + k4 * 4);
            As[(k4 * 4 + 0) * 130 + row] = v.x;
            As[(k4 * 4 + 1) * 130 + row] = v.y;
            As[(k4 * 4 + 2) * 130 + row] = v.z;
            As[(k4 * 4 + 3) * 130 + row] = v.w;
        }
#pragma unroll
        for (int i = 0; i < 2; i++) {
            int t4 = tid + i * 256;
            int k = t4 >> 5, n4 = t4 & 31;
            float4 v = *(const float4*)(W + (size_t)(kc + k) * N + n0 + n4 * 4);
            float* bp = &Bs[k * 256 + n4 * 8];
            *(float2*)(bp + 0) = make_float2(v.x, v.x);
            *(float2*)(bp + 2) = make_float2(v.y, v.y);
            *(float2*)(bp + 4) = make_float2(v.z, v.z);
            *(float2*)(bp + 6) = make_float2(v.w, v.w);
        }
        __syncthreads();
#pragma unroll 8
        for (int k = 0; k < 16; k++) {
            ull a0 = *(const ull*)&As[k * 130 + ty * 8 + 0];
            ull a1 = *(const ull*)&As[k * 130 + ty * 8 + 2];
            ull a2 = *(const ull*)&As[k * 130 + ty * 8 + 4];
            ull a3 = *(const ull*)&As[k * 130 + ty * 8 + 6];
#pragma unroll
            for (int j = 0; j < 8; j++) {
                ull b = *(const ull*)&Bs[k * 256 + 2 * tx + 32 * j];
                fma2(acc[0][j], a0, b);
                fma2(acc[1][j], a1, b);
                fma2(acc[2][j], a2, b);
                fma2(acc[3][j], a3, b);
            }
        }
        __syncthreads();
    }

#pragma unroll
    for (int p = 0; p < 4; p++) {
        size_t r0 = m0 + ty * 8 + 2 * p;
        float lo[8], hi[8];
#pragma unroll
        for (int j = 0; j < 8; j++) {
            unpack2(acc[p][j], lo[j], hi[j]);
            if (RELU) { lo[j] = fmaxf(lo[j], 0.f); hi[j] = fmaxf(hi[j], 0.f); }
        }
        if (NORM) {
            float sl = 0.f, sh2 = 0.f;
#pragma unroll
            for (int j = 0; j < 8; j++) {
                sl = fmaf(lo[j], lo[j], sl);
                sh2 = fmaf(hi[j], hi[j], sh2);
            }
#pragma unroll
            for (int off = 8; off > 0; off >>= 1) {
                sl += __shfl_xor_sync(0xffffffffu, sl, off);
                sh2 += __shfl_xor_sync(0xffffffffu, sh2, off);
            }
            float il = 1.f / fmaxf(sqrtf(sl), 1e-12f);
            float ih = 1.f / fmaxf(sqrtf(sh2), 1e-12f);
#pragma unroll
            for (int j = 0; j < 8; j++) {
                C[r0 * N + n0 + tx + 16 * j] = lo[j] * il;
                C[(r0 + 1) * N + n0 + tx + 16 * j] = hi[j] * ih;
            }
        } else {
#pragma unroll
            for (int j = 0; j < 8; j++) {
                C[r0 * N + n0 + tx + 16 * j] = lo[j];
                C[(r0 + 1) * N + n0 + tx + 16 * j] = hi[j];
            }
        }
    }
}

extern "C" void kernel_launch(void* const* d_in, const int* in_sizes, int n_in,
                              void* d_out, int out_size) {
    const float* x      = (const float*)d_in[0];
    const float* W_enc  = (const float*)d_in[1];
    const float* b_enc  = (const float*)d_in[2];
    const float* W_gc1  = (const float*)d_in[3];
    const float* b_gc1  = (const float*)d_in[4];
    const float* W_gc2  = (const float*)d_in[5];
    const float* b_gc2  = (const float*)d_in[6];
    const float* gamma1 = (const float*)d_in[7];
    const float* beta1  = (const float*)d_in[8];
    const float* gamma2 = (const float*)d_in[9];
    const float* beta2  = (const float*)d_in[10];
    const float* W_p1   = (const float*)d_in[11];
    const float* b_p1   = (const float*)d_in[12];
    const float* W_p2   = (const float*)d_in[13];
    const float* b_p2   = (const float*)d_in[14];
    float* out = (float*)d_out;

    // Resolve device addresses of __device__ globals (host shadow != device ptr).
    float *bufA = 0, *bufB = 0, *z = 0, *wp1t = 0, *wgt1 = 0, *wgt2 = 0;
    cudaGetSymbolAddress((void**)&bufA, g_bufA);
    cudaGetSymbolAddress((void**)&bufB, g_bufB);
    cudaGetSymbolAddress((void**)&z,    g_z);
    cudaGetSymbolAddress((void**)&wp1t, g_wp1t);
    cudaGetSymbolAddress((void**)&wgt1, g_wgt1);
    cudaGetSymbolAddress((void**)&wgt2, g_wgt2);

    cudaFuncSetAttribute(k_p1mma, cudaFuncAttributeMaxDynamicSharedMemorySize, P1_SMEM);
    cudaFuncSetAttribute(k_gcf<1>, cudaFuncAttributeMaxDynamicSharedMemorySize, GCF_SMEM);
    cudaFuncSetAttribute(k_gcf<2>, cudaFuncAttributeMaxDynamicSharedMemorySize, GCF_SMEM);

    int B = in_sizes[0] / 34;        // x is (B,17,2)
    if (B <= 0) return;
    int M17 = B * 17;
    int gF = (B + 7) / 8;
    double invN = 1.0 / ((double)B * 64.0);

    k_zero<<<1, 68>>>();
    k_tr<<<(1088 * 256 + 255) / 256, 256>>>(W_p1, wp1t);
    k_trg<<<16, 256>>>(W_gc1, wgt1);
    k_trg<<<16, 256>>>(W_gc2, wgt2);
    // BN1 stats from x (stats-only; y1 recomputed in gc1)
    k_stats<1><<<gF, 256>>>(x, W_enc, b_enc, B, 0);
    k_fin<<<1, 32>>>(gamma1, beta1, invN, 0);
    // gc1 fused: h2 = relu(bn1(enc+agg(x)) @ W_gc1 + b) -> bufB
    k_gcf<1><<<M17 / 128, 256, GCF_SMEM>>>(x, W_enc, b_enc, wgt1, b_gc1, bufB, M17);
    // BN2 stats from h2 (stats-only)
    k_stats<0><<<gF, 256>>>(bufB, 0, 0, B, 1);
    k_fin<<<1, 32>>>(gamma2, beta2, invN, 1);
    // gc2 fused: pooled = relu(bn2(h2+agg(h2)) @ W_gc2 + b), tf32 -> bufA
    k_gcf<2><<<M17 / 128, 256, GCF_SMEM>>>(bufB, 0, 0, wgt2, b_gc2, bufA, M17);
    // p1 (tf32 mma, L2-paired grid): z = relu(pooled @ W_p1 + b_p1) -> z
    k_p1mma<<<dim3(2, B / 128), 256, P1_SMEM>>>(bufA, wp1t, b_p1, z, B);
    // p2 + L2 normalize -> out (B,128)
    k_gemm128<0, 1><<<dim3(B / 128, 1), 256>>>(z, W_p2, b_p2, out, B, 128, 256);
}

// round 12
// speedup vs baseline: 1.3105x; 1.3105x over previous
#include <cuda_runtime.h>
#include <math.h>
#include <stdint.h>

#define BMAX 65536

// ---- scratch (allocation-free rule: __device__ globals) ----
__device__ __align__(16) float g_bufA[(size_t)BMAX * 17 * 64];
__device__ __align__(16) float g_bufB[(size_t)BMAX * 17 * 64];
__device__ __align__(16) float g_z[(size_t)BMAX * 256];
__device__ __align__(16) float g_wp1t[256 * 1088];   // W_p1^T (n-major), tf32
__device__ __align__(16) float g_wp2t[128 * 256];    // W_p2^T (n-major), tf32
__device__ __align__(16) float g_wgt1[64 * 64];      // W_gc1^T (n-major), tf32
__device__ __align__(16) float g_wgt2[64 * 64];      // W_gc2^T (n-major), tf32
__device__ double g_stats[68];
__device__ float g_scale1[17], g_shift1[17], g_scale2[17], g_shift2[17];

// ---- adjacency tables (I + A_norm) ----
__constant__ int   c_cnt[17] = {2,0,0,0,0,4,4,2,2,1,1,3,3,2,2,1,1};
__constant__ float c_w[17]   = {0.5f,0.f,0.f,0.f,0.f,0.25f,0.25f,0.5f,0.5f,1.f,1.f,
                                (1.f/3.f),(1.f/3.f),0.5f,0.5f,1.f,1.f};
__constant__ int   c_nb[17][4] = {
    {5,6,0,0},  {0,0,0,0}, {0,0,0,0}, {0,0,0,0}, {0,0,0,0},
    {7,6,11,0}, {8,5,12,0},
    {5,9,0,0},  {6,10,0,0},
    {7,0,0,0},  {8,0,0,0},
    {5,12,13,0},{6,11,14,0},
    {11,15,0,0},{12,16,0,0},
    {13,0,0,0}, {14,0,0,0}
};

// ---- helpers ----
__device__ __forceinline__ float rna_tf32(float v) {
    asm("cvt.rna.tf32.f32 %0, %1;" : "=f"(v) : "f"(v));
    return v;
}
__device__ __forceinline__ uint32_t s2u(const void* p) {
    uint32_t a;
    asm("{ .reg .u64 t; cvta.to.shared.u64 t, %1; cvt.u32.u64 %0, t; }" : "=r"(a) : "l"(p));
    return a;
}
#define MMA_TF32(acc, a0, a1, a2, a3, b0, b1) \
    asm volatile( \
        "mma.sync.aligned.m16n8k8.row.col.f32.tf32.tf32.f32 " \
        "{%0,%1,%2,%3}, {%4,%5,%6,%7}, {%8,%9}, {%0,%1,%2,%3};" \
        : "+f"(acc[0]), "+f"(acc[1]), "+f"(acc[2]), "+f"(acc[3]) \
        : "r"(a0), "r"(a1), "r"(a2), "r"(a3), "r"(b0), "r"(b1))

__global__ void k_zero() {
    if (threadIdx.x < 68) g_stats[threadIdx.x] = 0.0;
}

// ---- transpose W_p1 (1088x256) -> (256x1088), tf32 ----
__global__ void __launch_bounds__(256)
k_tr(const float* __restrict__ W, float* __restrict__ T) {
    int i = blockIdx.x * 256 + threadIdx.x;
    if (i >= 1088 * 256) return;
    int k = i >> 8, n = i & 255;
    T[(size_t)n * 1088 + k] = rna_tf32(W[i]);
}

// ---- transpose W_p2 (256x128) -> (128x256), tf32 ----
__global__ void __launch_bounds__(256)
k_tr2(const float* __restrict__ W, float* __restrict__ T) {
    int i = blockIdx.x * 256 + threadIdx.x;
    if (i >= 256 * 128) return;
    int k = i >> 7, n = i & 127;
    T[(size_t)n * 256 + k] = rna_tf32(W[i]);
}

// ---- transpose W_gc (64x64) -> (n-major 64x64), tf32 ----
__global__ void __launch_bounds__(256)
k_trg(const float* __restrict__ W, float* __restrict__ T) {
    int i = blockIdx.x * 256 + threadIdx.x;
    if (i >= 4096) return;
    int k = i >> 6, n = i & 63;
    T[n * 64 + k] = rna_tf32(W[i]);
}

// ---- fused elementwise: (optional encoder) + aggregation + BN stats ----
template <int ENC>
__global__ void __launch_bounds__(256)
k_fuse(const float* __restrict__ src, const float* __restrict__ W,
       const float* __restrict__ bvec, float* __restrict__ ydst, int B, int set) {
    __shared__ float h_sm[8 * 1156];
    __shared__ float ss[17], qq[17];
    int tid = threadIdx.x;
    int s0 = blockIdx.x * 8;
    if (tid < 17) { ss[tid] = 0.f; qq[tid] = 0.f; }

    for (int idx = tid; idx < 272; idx += 256) {
        int n = idx >> 4, c4 = idx & 15;
        float4 w0, w1, bb;
        if (ENC) {
            w0 = *(const float4*)(W + c4 * 4);
            w1 = *(const float4*)(W + 64 + c4 * 4);
            bb = *(const float4*)(bvec + c4 * 4);
        }
#pragma unroll
        for (int s = 0; s < 8; s++) {
            int e = s0 + s;
            if (e >= B) break;
            float4 v;
            if (ENC) {
                float x0 = src[((size_t)e * 17 + n) * 2];
                float x1 = src[((size_t)e * 17 + n) * 2 + 1];
                v.x = fmaxf(fmaf(x0, w0.x, fmaf(x1, w1.x, bb.x)), 0.f);
                v.y = fmaxf(fmaf(x0, w0.y, fmaf(x1, w1.y, bb.y)), 0.f);
                v.z = fmaxf(fmaf(x0, w0.z, fmaf(x1, w1.z, bb.z)), 0.f);
                v.w = fmaxf(fmaf(x0, w0.w, fmaf(x1, w1.w, bb.w)), 0.f);
            } else {
                v = *(const float4*)(src + ((size_t)e * 17 + n) * 64 + c4 * 4);
            }
            *(float4*)&h_sm[s * 1156 + n * 68 + c4 * 4] = v;
        }
    }
    __syncthreads();

    for (int idx = tid; idx < 272; idx += 256) {
        int n = idx >> 4, c4 = idx & 15;
        float w = c_w[n];
        int cnt = c_cnt[n];
        float sp = 0.f, qp = 0.f;
#pragma unroll
        for (int s = 0; s < 8; s++) {
            int e = s0 + s;
            if (e >= B) break;
            float4 acc = *(const float4*)&h_sm[s * 1156 + n * 68 + c4 * 4];
            for (int j = 0; j < cnt; j++) {
                const float4 hb = *(const float4*)&h_sm[s * 1156 + c_nb[n][j] * 68 + c4 * 4];
                acc.x = fmaf(w, hb.x, acc.x);
                acc.y = fmaf(w, hb.y, acc.y);
                acc.z = fmaf(w, hb.z, acc.z);
                acc.w = fmaf(w, hb.w, acc.w);
            }
            *(float4*)(ydst + ((size_t)e * 17 + n) * 64 + c4 * 4) = acc;
            sp += acc.x + acc.y + acc.z + acc.w;
            qp = fmaf(acc.x, acc.x, fmaf(acc.y, acc.y, fmaf(acc.z, acc.z, fmaf(acc.w, acc.w, qp))));
        }
        atomicAdd(&ss[n], sp);
        atomicAdd(&qq[n], qp);
    }
    __syncthreads();
    if (tid < 17) {
        atomicAdd(&g_stats[set * 34 + 2 * tid], (double)ss[tid]);
        atomicAdd(&g_stats[set * 34 + 2 * tid + 1], (double)qq[tid]);
    }
}

// ---- finalize BN stats -> fused scale/shift ----
__global__ void k_fin(const float* __restrict__ gamma, const float* __restrict__ beta,
                      double invN, int set) {
    int i = threadIdx.x;
    if (i >= 17) return;
    double s = g_stats[set * 34 + 2 * i];
    double q = g_stats[set * 34 + 2 * i + 1];
    double mean = s * invN;
    double var = q * invN - mean * mean;
    if (var < 0.0) var = 0.0;
    float inv = (float)(1.0 / sqrt(var + 1e-5));
    float sc = gamma[i] * inv;
    float sh = beta[i] - (float)mean * sc;
    if (set == 0) { g_scale1[i] = sc; g_shift1[i] = sh; }
    else          { g_scale2[i] = sc; g_shift2[i] = sh; }
}

// ---- gc layer via tf32 mma: C = relu(bn_affine(A) @ W + bias) ----
#define GC_PAD 68
#define GC_SMEM ((128 * GC_PAD + 64 * GC_PAD) * 4)
template <int AFF, int RND>
__global__ void __launch_bounds__(256)
k_gc(const float* __restrict__ A, const float* __restrict__ Wt,
     const float* __restrict__ bias, float* __restrict__ C, int M) {
    extern __shared__ float smf[];
    float* As = smf;                 // [128][GC_PAD]
    float* Ws = smf + 128 * GC_PAD;  // [64][GC_PAD]
    const int tid = threadIdx.x;
    const int w = tid >> 5, lane = tid & 31;
    const int gid = lane >> 2, tig = lane & 3;
    const size_t m0 = (size_t)blockIdx.x * 128;
    const int wm = (w >> 1) * 32, wn = (w & 1) * 32;

#pragma unroll
    for (int j = 0; j < 8; j++) {
        int u = tid + j * 256;
        int row = u >> 4, seg = u & 15;
        float4 v = *(const float4*)(A + (m0 + row) * 64 + seg * 4);
        if (AFF != 0) {
            int node = (int)((m0 + row) % 17);
            float sc = (AFF == 1) ? g_scale1[node] : g_scale2[node];
            float sh = (AFF == 1) ? g_shift1[node] : g_shift2[node];
            v.x = fmaf(v.x, sc, sh); v.y = fmaf(v.y, sc, sh);
            v.z = fmaf(v.z, sc, sh); v.w = fmaf(v.w, sc, sh);
        }
        float* ap = &As[row * GC_PAD + seg * 4];
        ap[0] = rna_tf32(v.x); ap[1] = rna_tf32(v.y);
        ap[2] = rna_tf32(v.z); ap[3] = rna_tf32(v.w);
    }
#pragma unroll
    for (int j = 0; j < 4; j++) {
        int u = tid + j * 256;
        int row = u >> 4, seg = u & 15;
        *(float4*)&Ws[row * GC_PAD + seg * 4] = *(const float4*)(Wt + row * 64 + seg * 4);
    }
    __syncthreads();

    float acc[2][4][4];
#pragma unroll
    for (int mi = 0; mi < 2; mi++)
#pragma unroll
        for (int ni = 0; ni < 4; ni++)
#pragma unroll
            for (int r = 0; r < 4; r++) acc[mi][ni][r] = 0.f;

#pragma unroll
    for (int ks = 0; ks < 8; ks++) {
        uint32_t af[2][4], bf[4][2];
#pragma unroll
        for (int mi = 0; mi < 2; mi++) {
            int rm = wm + mi * 16 + gid;
            af[mi][0] = __float_as_uint(As[rm * GC_PAD + ks * 8 + tig]);
            af[mi][1] = __float_as_uint(As[(rm + 8) * GC_PAD + ks * 8 + tig]);
            af[mi][2] = __float_as_uint(As[rm * GC_PAD + ks * 8 + tig + 4]);
            af[mi][3] = __float_as_uint(As[(rm + 8) * GC_PAD + ks * 8 + tig + 4]);
        }
#pragma unroll
        for (int ni = 0; ni < 4; ni++) {
            int rn = wn + ni * 8 + gid;
            bf[ni][0] = __float_as_uint(Ws[rn * GC_PAD + ks * 8 + tig]);
            bf[ni][1] = __float_as_uint(Ws[rn * GC_PAD + ks * 8 + tig + 4]);
        }
#pragma unroll
        for (int mi = 0; mi < 2; mi++)
#pragma unroll
            for (int ni = 0; ni < 4; ni++)
                MMA_TF32(acc[mi][ni], af[mi][0], af[mi][1], af[mi][2], af[mi][3],
                         bf[ni][0], bf[ni][1]);
    }

#pragma unroll
    for (int mi = 0; mi < 2; mi++) {
        size_t row = m0 + wm + mi * 16 + gid;
#pragma unroll
        for (int ni = 0; ni < 4; ni++) {
            int col = wn + ni * 8 + tig * 2;
            float b0 = __ldg(bias + col), b1 = __ldg(bias + col + 1);
            float2 v0, v1;
            v0.x = fmaxf(acc[mi][ni][0] + b0, 0.f);
            v0.y = fmaxf(acc[mi][ni][1] + b1, 0.f);
            v1.x = fmaxf(acc[mi][ni][2] + b0, 0.f);
            v1.y = fmaxf(acc[mi][ni][3] + b1, 0.f);
            if (RND) {
                v0.x = rna_tf32(v0.x); v0.y = rna_tf32(v0.y);
                v1.x = rna_tf32(v1.x); v1.y = rna_tf32(v1.y);
            }
            *(float2*)(C + row * 64 + col) = v0;
            *(float2*)(C + (row + 8) * 64 + col) = v1;
        }
    }
}

// ---- pool GEMM via tf32 mma, BM=128, BN=128, double-buffered cp.async ----
// KDIM: K (mult of 32). CN: C row stride. RELU; RND (tf32-round out); NORM (L2).
// grid: (gridDim.x = N/128, gridDim.y = M/128); m0 = blockIdx.y, n0 = blockIdx.x.
#define PM_STAGE_F (128 * 36)
#define PM_SMEM (2 * 2 * PM_STAGE_F * 4)
template <int KDIM, int CN, int RELU, int RND, int NORM>
__global__ void __launch_bounds__(256)
k_pmma(const float* __restrict__ A, const float* __restrict__ Bt,
       const float* __restrict__ bias, float* __restrict__ C) {
    extern __shared__ float smf[];
    const uint32_t sb = s2u(smf);
    const int tid = threadIdx.x;
    const int w = tid >> 5, lane = tid & 31;
    const int gid = lane >> 2, tig = lane & 3;
    const size_t m0 = (size_t)blockIdx.y * 128;
    const int n0 = blockIdx.x * 128;
    const int wm = (w >> 2) * 64, wn = (w & 3) * 32;
    const int NCH = KDIM / 32;

    float acc[4][4][4];
#pragma unroll
    for (int mi = 0; mi < 4; mi++)
#pragma unroll
        for (int ni = 0; ni < 4; ni++)
#pragma unroll
            for (int r = 0; r < 4; r++) acc[mi][ni][r] = 0.f;

    auto load_chunk = [&](int c, int s) {
        uint32_t base = sb + (uint32_t)(s * 2 * PM_STAGE_F) * 4;
        int kc = c * 32;
#pragma unroll
        for (int j = 0; j < 4; j++) {
            int u = tid + j * 256;
            int row = u >> 3, seg = u & 7;
            const float* src = A + (m0 + row) * KDIM + kc + seg * 4;
            uint32_t d = base + (uint32_t)(row * 36 + seg * 4) * 4;
            asm volatile("cp.async.cg.shared.global [%0], [%1], 16;" :: "r"(d), "l"(src) : "memory");
        }
#pragma unroll
        for (int j = 0; j < 4; j++) {
            int u = tid + j * 256;
            int row = u >> 3, seg = u & 7;
            const float* src = Bt + (size_t)(n0 + row) * KDIM + kc + seg * 4;
            uint32_t d = base + (uint32_t)(PM_STAGE_F + row * 36 + seg * 4) * 4;
            asm volatile("cp.async.cg.shared.global [%0], [%1], 16;" :: "r"(d), "l"(src) : "memory");
        }
        asm volatile("cp.async.commit_group;" ::: "memory");
    };

    load_chunk(0, 0);
    if (NCH > 1) load_chunk(1, 1);

    for (int c = 0; c < NCH; c++) {
        int s = c & 1;
        if (c == NCH - 1) asm volatile("cp.async.wait_group 0;" ::: "memory");
        else              asm volatile("cp.async.wait_group 1;" ::: "memory");
        __syncthreads();
        const float* As_s = smf + s * 2 * PM_STAGE_F;
        const float* Bs_s = As_s + PM_STAGE_F;
#pragma unroll
        for (int ks = 0; ks < 4; ks++) {
            uint32_t af[4][4], bf[4][2];
#pragma unroll
            for (int mi = 0; mi < 4; mi++) {
                int rm = wm + mi * 16 + gid;
                af[mi][0] = __float_as_uint(As_s[rm * 36 + ks * 8 + tig]);
                af[mi][1] = __float_as_uint(As_s[(rm + 8) * 36 + ks * 8 + tig]);
                af[mi][2] = __float_as_uint(As_s[rm * 36 + ks * 8 + tig + 4]);
                af[mi][3] = __float_as_uint(As_s[(rm + 8) * 36 + ks * 8 + tig + 4]);
            }
#pragma unroll
            for (int ni = 0; ni < 4; ni++) {
                int rn = wn + ni * 8 + gid;
                bf[ni][0] = __float_as_uint(Bs_s[rn * 36 + ks * 8 + tig]);
                bf[ni][1] = __float_as_uint(Bs_s[rn * 36 + ks * 8 + tig + 4]);
            }
#pragma unroll
            for (int mi = 0; mi < 4; mi++)
#pragma unroll
                for (int ni = 0; ni < 4; ni++)
                    MMA_TF32(acc[mi][ni], af[mi][0], af[mi][1], af[mi][2], af[mi][3],
                             bf[ni][0], bf[ni][1]);
        }
        __syncthreads();
        if (c + 2 < NCH) load_chunk(c + 2, s);
    }

    // add bias (and relu) into acc
#pragma unroll
    for (int mi = 0; mi < 4; mi++)
#pragma unroll
        for (int ni = 0; ni < 4; ni++) {
            int col = n0 + wn + ni * 8 + tig * 2;
            float b0 = __ldg(bias + col), b1 = __ldg(bias + col + 1);
            acc[mi][ni][0] += b0; acc[mi][ni][1] += b1;
            acc[mi][ni][2] += b0; acc[mi][ni][3] += b1;
            if (RELU) {
#pragma unroll
                for (int r = 0; r < 4; r++) acc[mi][ni][r] = fmaxf(acc[mi][ni][r], 0.f);
            }
        }

    float rs[4][2];  // per-(mi, row/row+8) inverse norms
    if (NORM) {
        float* rowssq = smf;   // reuse smem (all warps past last read)
        for (int i = tid; i < 128; i += 256) rowssq[i] = 0.f;
        __syncthreads();
#pragma unroll
        for (int mi = 0; mi < 4; mi++) {
            float p0 = 0.f, p1 = 0.f;
#pragma unroll
            for (int ni = 0; ni < 4; ni++) {
                p0 = fmaf(acc[mi][ni][0], acc[mi][ni][0], fmaf(acc[mi][ni][1], acc[mi][ni][1], p0));
                p1 = fmaf(acc[mi][ni][2], acc[mi][ni][2], fmaf(acc[mi][ni][3], acc[mi][ni][3], p1));
            }
            atomicAdd(&rowssq[wm + mi * 16 + gid], p0);
            atomicAdd(&rowssq[wm + mi * 16 + gid + 8], p1);
        }
        __syncthreads();
#pragma unroll
        for (int mi = 0; mi < 4; mi++) {
            rs[mi][0] = 1.f / fmaxf(sqrtf(rowssq[wm + mi * 16 + gid]), 1e-12f);
            rs[mi][1] = 1.f / fmaxf(sqrtf(rowssq[wm + mi * 16 + gid + 8]), 1e-12f);
        }
    }

#pragma unroll
    for (int mi = 0; mi < 4; mi++) {
        size_t row = m0 + wm + mi * 16 + gid;
#pragma unroll
        for (int ni = 0; ni < 4; ni++) {
            int col = n0 + wn + ni * 8 + tig * 2;
            float2 v0, v1;
            v0.x = acc[mi][ni][0]; v0.y = acc[mi][ni][1];
            v1.x = acc[mi][ni][2]; v1.y = acc[mi][ni][3];
            if (NORM) {
                v0.x *= rs[mi][0]; v0.y *= rs[mi][0];
                v1.x *= rs[mi][1]; v1.y *= rs[mi][1];
            }
            if (RND) {
                v0.x = rna_tf32(v0.x); v0.y = rna_tf32(v0.y);
                v1.x = rna_tf32(v1.x); v1.y = rna_tf32(v1.y);
            }
            *(float2*)(C + row * CN + col) = v0;
            *(float2*)(C + (row + 8) * CN + col) = v1;
        }
    }
}

extern "C" void kernel_launch(void* const* d_in, const int* in_sizes, int n_in,
                              void* d_out, int out_size) {
    const float* x      = (const float*)d_in[0];
    const float* W_enc  = (const float*)d_in[1];
    const float* b_enc  = (const float*)d_in[2];
    const float* W_gc1  = (const float*)d_in[3];
    const float* b_gc1  = (const float*)d_in[4];
    const float* W_gc2  = (const float*)d_in[5];
    const float* b_gc2  = (const float*)d_in[6];
    const float* gamma1 = (const float*)d_in[7];
    const float* beta1  = (const float*)d_in[8];
    const float* gamma2 = (const float*)d_in[9];
    const float* beta2  = (const float*)d_in[10];
    const float* W_p1   = (const float*)d_in[11];
    const float* b_p1   = (const float*)d_in[12];
    const float* W_p2   = (const float*)d_in[13];
    const float* b_p2   = (const float*)d_in[14];
    float* out = (float*)d_out;

    // Resolve device addresses of __device__ globals (host shadow != device ptr).
    float *bufA = 0, *bufB = 0, *z = 0, *wp1t = 0, *wp2t = 0, *wgt1 = 0, *wgt2 = 0;
    cudaGetSymbolAddress((void**)&bufA, g_bufA);
    cudaGetSymbolAddress((void**)&bufB, g_bufB);
    cudaGetSymbolAddress((void**)&z,    g_z);
    cudaGetSymbolAddress((void**)&wp1t, g_wp1t);
    cudaGetSymbolAddress((void**)&wp2t, g_wp2t);
    cudaGetSymbolAddress((void**)&wgt1, g_wgt1);
    cudaGetSymbolAddress((void**)&wgt2, g_wgt2);

    cudaFuncSetAttribute((const void*)k_pmma<1088, 256, 1, 1, 0>,
                         cudaFuncAttributeMaxDynamicSharedMemorySize, PM_SMEM);
    cudaFuncSetAttribute((const void*)k_pmma<256, 128, 0, 0, 1>,
                         cudaFuncAttributeMaxDynamicSharedMemorySize, PM_SMEM);
    cudaFuncSetAttribute((const void*)k_gc<1, 0>,
                         cudaFuncAttributeMaxDynamicSharedMemorySize, GC_SMEM);
    cudaFuncSetAttribute((const void*)k_gc<2, 1>,
                         cudaFuncAttributeMaxDynamicSharedMemorySize, GC_SMEM);

    int B = in_sizes[0] / 34;        // x is (B,17,2)
    if (B <= 0) return;
    int M17 = B * 17;
    int gF = (B + 7) / 8;
    double invN = 1.0 / ((double)B * 64.0);

    k_zero<<<1, 68>>>();
    k_tr<<<(1088 * 256 + 255) / 256, 256>>>(W_p1, wp1t);
    k_tr2<<<(256 * 128 + 255) / 256, 256>>>(W_p2, wp2t);
    k_trg<<<16, 256>>>(W_gc1, wgt1);
    k_trg<<<16, 256>>>(W_gc2, wgt2);
    // enc + agg + BN1 stats -> y1 in bufA
    k_fuse<1><<<gF, 256>>>(x, W_enc, b_enc, bufA, B, 0);
    k_fin<<<1, 32>>>(gamma1, beta1, invN, 0);
    // gc1 (tf32 mma): h2 = relu(bn1(y1) @ W_gc1 + b) -> bufB
    k_gc<1, 0><<<M17 / 128, 256, GC_SMEM>>>(bufA, wgt1, b_gc1, bufB, M17);
    // agg(h2) + BN2 stats -> y2 in bufA
    k_fuse<0><<<gF, 256>>>(bufB, 0, 0, bufA, B, 1);
    k_fin<<<1, 32>>>(gamma2, beta2, invN, 1);
    // gc2 (tf32 mma): pooled = relu(bn2(y2) @ W_gc2 + b), tf32-rounded -> bufB
    k_gc<2, 1><<<M17 / 128, 256, GC_SMEM>>>(bufA, wgt2, b_gc2, bufB, M17);
    // p1 (tf32 mma, N-pair-adjacent grid): z = relu(pooled @ W_p1 + b_p1), tf32 -> z
    k_pmma<1088, 256, 1, 1, 0><<<dim3(2, B / 128), 256, PM_SMEM>>>(bufB, wp1t, b_p1, z);
    // p2 (tf32 mma) + fused L2 normalize -> out (B,128)
    k_pmma<256, 128, 0, 0, 1><<<dim3(1, B / 128), 256, PM_SMEM>>>(z, wp2t, b_p2, out);
}

// round 13
// speedup vs baseline: 1.5692x; 1.1974x over previous
#include <cuda_runtime.h>
#include <cuda_fp16.h>
#include <math.h>
#include <stdint.h>

#define BMAX 65536

// ---- scratch (allocation-free rule: __device__ globals) ----
__device__ __align__(16) __half g_bufA[(size_t)BMAX * 17 * 64];
__device__ __align__(16) __half g_bufB[(size_t)BMAX * 17 * 64];
__device__ __align__(16) __half g_z[(size_t)BMAX * 256];
__device__ __align__(16) __half g_wp1t[256 * 1088];   // W_p1^T (n-major), fp16
__device__ __align__(16) __half g_wp2t[128 * 256];    // W_p2^T (n-major), fp16
__device__ __align__(16) float g_wgt1[64 * 64];       // W_gc1^T (n-major), tf32
__device__ __align__(16) float g_wgt2[64 * 64];       // W_gc2^T (n-major), tf32
__device__ double g_stats[68];
__device__ float g_scale1[17], g_shift1[17], g_scale2[17], g_shift2[17];

// ---- adjacency tables (I + A_norm) ----
__constant__ int   c_cnt[17] = {2,0,0,0,0,4,4,2,2,1,1,3,3,2,2,1,1};
__constant__ float c_w[17]   = {0.5f,0.f,0.f,0.f,0.f,0.25f,0.25f,0.5f,0.5f,1.f,1.f,
                                (1.f/3.f),(1.f/3.f),0.5f,0.5f,1.f,1.f};
__constant__ int   c_nb[17][4] = {
    {5,6,0,0},  {0,0,0,0}, {0,0,0,0}, {0,0,0,0}, {0,0,0,0},
    {7,6,11,0}, {8,5,12,0},
    {5,9,0,0},  {6,10,0,0},
    {7,0,0,0},  {8,0,0,0},
    {5,12,13,0},{6,11,14,0},
    {11,15,0,0},{12,16,0,0},
    {13,0,0,0}, {14,0,0,0}
};

// ---- helpers ----
__device__ __forceinline__ float rna_tf32(float v) {
    asm("cvt.rna.tf32.f32 %0, %1;" : "=f"(v) : "f"(v));
    return v;
}
__device__ __forceinline__ uint32_t s2u(const void* p) {
    uint32_t a;
    asm("{ .reg .u64 t; cvta.to.shared.u64 t, %1; cvt.u32.u64 %0, t; }" : "=r"(a) : "l"(p));
    return a;
}
__device__ __forceinline__ uint32_t lds32(uint32_t addr) {
    uint32_t v;
    asm volatile("ld.shared.b32 %0, [%1];" : "=r"(v) : "r"(addr));
    return v;
}
// XOR swizzle on 16B chunks: row-of-64B, 4 chunks; conflict-free fragment quads.
__device__ __forceinline__ uint32_t swz(int row, int chunk) {
    return (uint32_t)(row * 64 + ((chunk ^ ((row >> 1) & 3)) << 4));
}
#define MMA_TF32(acc, a0, a1, a2, a3, b0, b1) \
    asm volatile( \
        "mma.sync.aligned.m16n8k8.row.col.f32.tf32.tf32.f32 " \
        "{%0,%1,%2,%3}, {%4,%5,%6,%7}, {%8,%9}, {%0,%1,%2,%3};" \
        : "+f"(acc[0]), "+f"(acc[1]), "+f"(acc[2]), "+f"(acc[3]) \
        : "r"(a0), "r"(a1), "r"(a2), "r"(a3), "r"(b0), "r"(b1))
#define MMA_F16(acc, a0, a1, a2, a3, b0, b1) \
    asm volatile( \
        "mma.sync.aligned.m16n8k16.row.col.f32.f16.f16.f32 " \
        "{%0,%1,%2,%3}, {%4,%5,%6,%7}, {%8,%9}, {%0,%1,%2,%3};" \
        : "+f"(acc[0]), "+f"(acc[1]), "+f"(acc[2]), "+f"(acc[3]) \
        : "r"(a0), "r"(a1), "r"(a2), "r"(a3), "r"(b0), "r"(b1))

__global__ void k_zero() {
    if (threadIdx.x < 68) g_stats[threadIdx.x] = 0.0;
}

// ---- transpose W_p1 (1088x256) -> (256x1088), fp16 ----
__global__ void __launch_bounds__(256)
k_tr(const float* __restrict__ W, __half* __restrict__ T) {
    int i = blockIdx.x * 256 + threadIdx.x;
    if (i >= 1088 * 256) return;
    int k = i >> 8, n = i & 255;
    T[(size_t)n * 1088 + k] = __float2half_rn(W[i]);
}

// ---- transpose W_p2 (256x128) -> (128x256), fp16 ----
__global__ void __launch_bounds__(256)
k_tr2(const float* __restrict__ W, __half* __restrict__ T) {
    int i = blockIdx.x * 256 + threadIdx.x;
    if (i >= 256 * 128) return;
    int k = i >> 7, n = i & 127;
    T[(size_t)n * 256 + k] = __float2half_rn(W[i]);
}

// ---- transpose W_gc (64x64) -> (n-major 64x64), tf32 ----
__global__ void __launch_bounds__(256)
k_trg(const float* __restrict__ W, float* __restrict__ T) {
    int i = blockIdx.x * 256 + threadIdx.x;
    if (i >= 4096) return;
    int k = i >> 6, n = i & 63;
    T[n * 64 + k] = rna_tf32(W[i]);
}

// ---- fused elementwise: (optional encoder) + aggregation + BN stats ----
// ENC=1: src = x (float, B x 17 x 2); ENC=0: src = h (half, B x 17 x 64).
// Writes y = h + agg(h) as fp16 to ydst; per-node sum/sumsq (fp32/double) to g_stats.
template <int ENC>
__global__ void __launch_bounds__(256)
k_fuse(const void* __restrict__ src, const float* __restrict__ W,
       const float* __restrict__ bvec, __half* __restrict__ ydst, int B, int set) {
    __shared__ float h_sm[8 * 1156];
    __shared__ float ss[17], qq[17];
    int tid = threadIdx.x;
    int s0 = blockIdx.x * 8;
    if (tid < 17) { ss[tid] = 0.f; qq[tid] = 0.f; }

    for (int idx = tid; idx < 272; idx += 256) {
        int n = idx >> 4, c4 = idx & 15;
        float4 w0, w1, bb;
        if (ENC) {
            w0 = *(const float4*)(W + c4 * 4);
            w1 = *(const float4*)(W + 64 + c4 * 4);
            bb = *(const float4*)(bvec + c4 * 4);
        }
#pragma unroll
        for (int s = 0; s < 8; s++) {
            int e = s0 + s;
            if (e >= B) break;
            float4 v;
            if (ENC) {
                const float* xf = (const float*)src;
                float x0 = xf[((size_t)e * 17 + n) * 2];
                float x1 = xf[((size_t)e * 17 + n) * 2 + 1];
                v.x = fmaxf(fmaf(x0, w0.x, fmaf(x1, w1.x, bb.x)), 0.f);
                v.y = fmaxf(fmaf(x0, w0.y, fmaf(x1, w1.y, bb.y)), 0.f);
                v.z = fmaxf(fmaf(x0, w0.z, fmaf(x1, w1.z, bb.z)), 0.f);
                v.w = fmaxf(fmaf(x0, w0.w, fmaf(x1, w1.w, bb.w)), 0.f);
            } else {
                const __half2* hp = (const __half2*)((const __half*)src +
                                     ((size_t)e * 17 + n) * 64 + c4 * 4);
                float2 f0 = __half22float2(hp[0]);
                float2 f1 = __half22float2(hp[1]);
                v = make_float4(f0.x, f0.y, f1.x, f1.y);
            }
            *(float4*)&h_sm[s * 1156 + n * 68 + c4 * 4] = v;
        }
    }
    __syncthreads();

    for (int idx = tid; idx < 272; idx += 256) {
        int n = idx >> 4, c4 = idx & 15;
        float w = c_w[n];
        int cnt = c_cnt[n];
        float sp = 0.f, qp = 0.f;
#pragma unroll
        for (int s = 0; s < 8; s++) {
            int e = s0 + s;
            if (e >= B) break;
            float4 acc = *(const float4*)&h_sm[s * 1156 + n * 68 + c4 * 4];
            for (int j = 0; j < cnt; j++) {
                const float4 hb = *(const float4*)&h_sm[s * 1156 + c_nb[n][j] * 68 + c4 * 4];
                acc.x = fmaf(w, hb.x, acc.x);
                acc.y = fmaf(w, hb.y, acc.y);
                acc.z = fmaf(w, hb.z, acc.z);
                acc.w = fmaf(w, hb.w, acc.w);
            }
            __half2* yp = (__half2*)(ydst + ((size_t)e * 17 + n) * 64 + c4 * 4);
            yp[0] = __floats2half2_rn(acc.x, acc.y);
            yp[1] = __floats2half2_rn(acc.z, acc.w);
            sp += acc.x + acc.y + acc.z + acc.w;
            qp = fmaf(acc.x, acc.x, fmaf(acc.y, acc.y, fmaf(acc.z, acc.z, fmaf(acc.w, acc.w, qp))));
        }
        atomicAdd(&ss[n], sp);
        atomicAdd(&qq[n], qp);
    }
    __syncthreads();
    if (tid < 17) {
        atomicAdd(&g_stats[set * 34 + 2 * tid], (double)ss[tid]);
        atomicAdd(&g_stats[set * 34 + 2 * tid + 1], (double)qq[tid]);
    }
}

// ---- finalize BN stats -> fused scale/shift ----
__global__ void k_fin(const float* __restrict__ gamma, const float* __restrict__ beta,
                      double invN, int set) {
    int i = threadIdx.x;
    if (i >= 17) return;
    double s = g_stats[set * 34 + 2 * i];
    double q = g_stats[set * 34 + 2 * i + 1];
    double mean = s * invN;
    double var = q * invN - mean * mean;
    if (var < 0.0) var = 0.0;
    float inv = (float)(1.0 / sqrt(var + 1e-5));
    float sc = gamma[i] * inv;
    float sh = beta[i] - (float)mean * sc;
    if (set == 0) { g_scale1[i] = sc; g_shift1[i] = sh; }
    else          { g_scale2[i] = sc; g_shift2[i] = sh; }
}

// ---- gc layer via tf32 mma: C = relu(bn_affine(A) @ W + bias), half I/O ----
#define GC_PAD 68
#define GC_SMEM ((128 * GC_PAD + 64 * GC_PAD) * 4)
template <int AFF>
__global__ void __launch_bounds__(256)
k_gc(const __half* __restrict__ A, const float* __restrict__ Wt,
     const float* __restrict__ bias, __half* __restrict__ C, int M) {
    extern __shared__ float smf[];
    float* As = smf;                 // [128][GC_PAD]
    float* Ws = smf + 128 * GC_PAD;  // [64][GC_PAD]
    const int tid = threadIdx.x;
    const int w = tid >> 5, lane = tid & 31;
    const int gid = lane >> 2, tig = lane & 3;
    const size_t m0 = (size_t)blockIdx.x * 128;
    const int wm = (w >> 1) * 32, wn = (w & 1) * 32;

#pragma unroll
    for (int j = 0; j < 8; j++) {
        int u = tid + j * 256;
        int row = u >> 4, seg = u & 15;
        const __half2* hp = (const __half2*)(A + (m0 + row) * 64 + seg * 4);
        float2 f0 = __half22float2(hp[0]);
        float2 f1 = __half22float2(hp[1]);
        float4 v = make_float4(f0.x, f0.y, f1.x, f1.y);
        if (AFF != 0) {
            int node = (int)((m0 + row) % 17);
            float sc = (AFF == 1) ? g_scale1[node] : g_scale2[node];
            float sh = (AFF == 1) ? g_shift1[node] : g_shift2[node];
            v.x = fmaf(v.x, sc, sh); v.y = fmaf(v.y, sc, sh);
            v.z = fmaf(v.z, sc, sh); v.w = fmaf(v.w, sc, sh);
        }
        float* ap = &As[row * GC_PAD + seg * 4];
        ap[0] = rna_tf32(v.x); ap[1] = rna_tf32(v.y);
        ap[2] = rna_tf32(v.z); ap[3] = rna_tf32(v.w);
    }
#pragma unroll
    for (int j = 0; j < 4; j++) {
        int u = tid + j * 256;
        int row = u >> 4, seg = u & 15;
        *(float4*)&Ws[row * GC_PAD + seg * 4] = *(const float4*)(Wt + row * 64 + seg * 4);
    }
    __syncthreads();

    float acc[2][4][4];
#pragma unroll
    for (int mi = 0; mi < 2; mi++)
#pragma unroll
        for (int ni = 0; ni < 4; ni++)
#pragma unroll
            for (int r = 0; r < 4; r++) acc[mi][ni][r] = 0.f;

#pragma unroll
    for (int ks = 0; ks < 8; ks++) {
        uint32_t af[2][4], bf[4][2];
#pragma unroll
        for (int mi = 0; mi < 2; mi++) {
            int rm = wm + mi * 16 + gid;
            af[mi][0] = __float_as_uint(As[rm * GC_PAD + ks * 8 + tig]);
            af[mi][1] = __float_as_uint(As[(rm + 8) * GC_PAD + ks * 8 + tig]);
            af[mi][2] = __float_as_uint(As[rm * GC_PAD + ks * 8 + tig + 4]);
            af[mi][3] = __float_as_uint(As[(rm + 8) * GC_PAD + ks * 8 + tig + 4]);
        }
#pragma unroll
        for (int ni = 0; ni < 4; ni++) {
            int rn = wn + ni * 8 + gid;
            bf[ni][0] = __float_as_uint(Ws[rn * GC_PAD + ks * 8 + tig]);
            bf[ni][1] = __float_as_uint(Ws[rn * GC_PAD + ks * 8 + tig + 4]);
        }
#pragma unroll
        for (int mi = 0; mi < 2; mi++)
#pragma unroll
            for (int ni = 0; ni < 4; ni++)
                MMA_TF32(acc[mi][ni], af[mi][0], af[mi][1], af[mi][2], af[mi][3],
                         bf[ni][0], bf[ni][1]);
    }

#pragma unroll
    for (int mi = 0; mi < 2; mi++) {
        size_t row = m0 + wm + mi * 16 + gid;
#pragma unroll
        for (int ni = 0; ni < 4; ni++) {
            int col = wn + ni * 8 + tig * 2;
            float b0 = __ldg(bias + col), b1 = __ldg(bias + col + 1);
            float r00 = fmaxf(acc[mi][ni][0] + b0, 0.f);
            float r01 = fmaxf(acc[mi][ni][1] + b1, 0.f);
            float r10 = fmaxf(acc[mi][ni][2] + b0, 0.f);
            float r11 = fmaxf(acc[mi][ni][3] + b1, 0.f);
            *(__half2*)(C + row * 64 + col) = __floats2half2_rn(r00, r01);
            *(__half2*)(C + (row + 8) * 64 + col) = __floats2half2_rn(r10, r11);
        }
    }
}

// ---- pool GEMM via fp16 mma (m16n8k16), BM=128, BN=128, double-buffered cp.async ----
// A, Bt fp16 (k-contiguous rows). KDIM halves per row (mult of 32). CN = C row stride.
// OUTHALF: write half2; NORM: fused L2-normalize, write float.
#define PH_STAGE 16384                 // A(8KB) + B(8KB) per stage
#define PH_SMEM (2 * PH_STAGE)
template <int KDIM, int CN, int RELU, int OUTHALF, int NORM>
__global__ void __launch_bounds__(256)
k_pmma(const __half* __restrict__ A, const __half* __restrict__ Bt,
       const float* __restrict__ bias, void* __restrict__ Cout) {
    extern __shared__ float smf[];
    const uint32_t sb = s2u(smf);
    const int tid = threadIdx.x;
    const int w = tid >> 5, lane = tid & 31;
    const int gid = lane >> 2, tig = lane & 3;
    const size_t m0 = (size_t)blockIdx.y * 128;
    const int n0 = blockIdx.x * 128;
    const int wm = (w >> 2) * 64, wn = (w & 3) * 32;
    const int NCH = KDIM / 32;

    float acc[4][4][4];
#pragma unroll
    for (int mi = 0; mi < 4; mi++)
#pragma unroll
        for (int ni = 0; ni < 4; ni++)
#pragma unroll
            for (int r = 0; r < 4; r++) acc[mi][ni][r] = 0.f;

    auto load_chunk = [&](int c, int s) {
        uint32_t base = sb + (uint32_t)s * PH_STAGE;
        int kc = c * 32;
#pragma unroll
        for (int j = 0; j < 2; j++) {            // A: 128 rows x 4 x 16B
            int u = tid + j * 256;
            int row = u >> 2, cc = u & 3;
            const __half* src = A + (m0 + row) * (size_t)KDIM + kc + cc * 8;
            uint32_t d = base + swz(row, cc);
            asm volatile("cp.async.cg.shared.global [%0], [%1], 16;" :: "r"(d), "l"(src) : "memory");
        }
#pragma unroll
        for (int j = 0; j < 2; j++) {            // B: 128 n-rows x 4 x 16B
            int u = tid + j * 256;
            int row = u >> 2, cc = u & 3;
            const __half* src = Bt + (size_t)(n0 + row) * KDIM + kc + cc * 8;
            uint32_t d = base + 8192 + swz(row, cc);
            asm volatile("cp.async.cg.shared.global [%0], [%1], 16;" :: "r"(d), "l"(src) : "memory");
        }
        asm volatile("cp.async.commit_group;" ::: "memory");
    };

    load_chunk(0, 0);
    if (NCH > 1) load_chunk(1, 1);

    for (int c = 0; c < NCH; c++) {
        int s = c & 1;
        if (c == NCH - 1) asm volatile("cp.async.wait_group 0;" ::: "memory");
        else              asm volatile("cp.async.wait_group 1;" ::: "memory");
        __syncthreads();
        uint32_t baseA = sb + (uint32_t)s * PH_STAGE;
        uint32_t baseB = baseA + 8192;
#pragma unroll
        for (int ks = 0; ks < 2; ks++) {
            int c0 = 2 * ks, c1 = 2 * ks + 1;
            uint32_t af[4][4], bf[4][2];
#pragma unroll
            for (int mi = 0; mi < 4; mi++) {
                int r0 = wm + mi * 16 + gid, r1 = r0 + 8;
                af[mi][0] = lds32(baseA + swz(r0, c0) + tig * 4);
                af[mi][1] = lds32(baseA + swz(r1, c0) + tig * 4);
                af[mi][2] = lds32(baseA + swz(r0, c1) + tig * 4);
                af[mi][3] = lds32(baseA + swz(r1, c1) + tig * 4);
            }
#pragma unroll
            for (int ni = 0; ni < 4; ni++) {
                int rn = wn + ni * 8 + gid;
                bf[ni][0] = lds32(baseB + swz(rn, c0) + tig * 4);
                bf[ni][1] = lds32(baseB + swz(rn, c1) + tig * 4);
            }
#pragma unroll
            for (int mi = 0; mi < 4; mi++)
#pragma unroll
                for (int ni = 0; ni < 4; ni++)
                    MMA_F16(acc[mi][ni], af[mi][0], af[mi][1], af[mi][2], af[mi][3],
                            bf[ni][0], bf[ni][1]);
        }
        __syncthreads();
        if (c + 2 < NCH) load_chunk(c + 2, s);
    }

    // bias (+relu)
#pragma unroll
    for (int mi = 0; mi < 4; mi++)
#pragma unroll
        for (int ni = 0; ni < 4; ni++) {
            int col = n0 + wn + ni * 8 + tig * 2;
            float b0 = __ldg(bias + col), b1 = __ldg(bias + col + 1);
            acc[mi][ni][0] += b0; acc[mi][ni][1] += b1;
            acc[mi][ni][2] += b0; acc[mi][ni][3] += b1;
            if (RELU) {
#pragma unroll
                for (int r = 0; r < 4; r++) acc[mi][ni][r] = fmaxf(acc[mi][ni][r], 0.f);
            }
        }

    float rs[4][2];
    if (NORM) {
        float* rowssq = smf;   // reuse smem (safe: all pending reads synced above)
        for (int i = tid; i < 128; i += 256) rowssq[i] = 0.f;
        __syncthreads();
#pragma unroll
        for (int mi = 0; mi < 4; mi++) {
            float p0 = 0.f, p1 = 0.f;
#pragma unroll
            for (int ni = 0; ni < 4; ni++) {
                p0 = fmaf(acc[mi][ni][0], acc[mi][ni][0], fmaf(acc[mi][ni][1], acc[mi][ni][1], p0));
                p1 = fmaf(acc[mi][ni][2], acc[mi][ni][2], fmaf(acc[mi][ni][3], acc[mi][ni][3], p1));
            }
            atomicAdd(&rowssq[wm + mi * 16 + gid], p0);
            atomicAdd(&rowssq[wm + mi * 16 + gid + 8], p1);
        }
        __syncthreads();
#pragma unroll
        for (int mi = 0; mi < 4; mi++) {
            rs[mi][0] = 1.f / fmaxf(sqrtf(rowssq[wm + mi * 16 + gid]), 1e-12f);
            rs[mi][1] = 1.f / fmaxf(sqrtf(rowssq[wm + mi * 16 + gid + 8]), 1e-12f);
        }
    }

#pragma unroll
    for (int mi = 0; mi < 4; mi++) {
        size_t row = m0 + wm + mi * 16 + gid;
#pragma unroll
        for (int ni = 0; ni < 4; ni++) {
            int col = n0 + wn + ni * 8 + tig * 2;
            float v00 = acc[mi][ni][0], v01 = acc[mi][ni][1];
            float v10 = acc[mi][ni][2], v11 = acc[mi][ni][3];
            if (NORM) {
                v00 *= rs[mi][0]; v01 *= rs[mi][0];
                v10 *= rs[mi][1]; v11 *= rs[mi][1];
            }
            if (OUTHALF) {
                __half* Ch = (__half*)Cout;
                *(__half2*)(Ch + row * CN + col) = __floats2half2_rn(v00, v01);
                *(__half2*)(Ch + (row + 8) * CN + col) = __floats2half2_rn(v10, v11);
            } else {
                float* Cf = (float*)Cout;
                *(float2*)(Cf + row * CN + col) = make_float2(v00, v01);
                *(float2*)(Cf + (row + 8) * CN + col) = make_float2(v10, v11);
            }
        }
    }
}

extern "C" void kernel_launch(void* const* d_in, const int* in_sizes, int n_in,
                              void* d_out, int out_size) {
    const float* x      = (const float*)d_in[0];
    const float* W_enc  = (const float*)d_in[1];
    const float* b_enc  = (const float*)d_in[2];
    const float* W_gc1  = (const float*)d_in[3];
    const float* b_gc1  = (const float*)d_in[4];
    const float* W_gc2  = (const float*)d_in[5];
    const float* b_gc2  = (const float*)d_in[6];
    const float* gamma1 = (const float*)d_in[7];
    const float* beta1  = (const float*)d_in[8];
    const float* gamma2 = (const float*)d_in[9];
    const float* beta2  = (const float*)d_in[10];
    const float* W_p1   = (const float*)d_in[11];
    const float* b_p1   = (const float*)d_in[12];
    const float* W_p2   = (const float*)d_in[13];
    const float* b_p2   = (const float*)d_in[14];
    float* out = (float*)d_out;

    // Resolve device addresses of __device__ globals (host shadow != device ptr).
    __half *bufA = 0, *bufB = 0, *z = 0, *wp1t = 0, *wp2t = 0;
    float *wgt1 = 0, *wgt2 = 0;
    cudaGetSymbolAddress((void**)&bufA, g_bufA);
    cudaGetSymbolAddress((void**)&bufB, g_bufB);
    cudaGetSymbolAddress((void**)&z,    g_z);
    cudaGetSymbolAddress((void**)&wp1t, g_wp1t);
    cudaGetSymbolAddress((void**)&wp2t, g_wp2t);
    cudaGetSymbolAddress((void**)&wgt1, g_wgt1);
    cudaGetSymbolAddress((void**)&wgt2, g_wgt2);

    cudaFuncSetAttribute((const void*)k_pmma<1088, 256, 1, 1, 0>,
                         cudaFuncAttributeMaxDynamicSharedMemorySize, PH_SMEM);
    cudaFuncSetAttribute((const void*)k_pmma<256, 128, 0, 0, 1>,
                         cudaFuncAttributeMaxDynamicSharedMemorySize, PH_SMEM);
    cudaFuncSetAttribute((const void*)k_gc<1>,
                         cudaFuncAttributeMaxDynamicSharedMemorySize, GC_SMEM);
    cudaFuncSetAttribute((const void*)k_gc<2>,
                         cudaFuncAttributeMaxDynamicSharedMemorySize, GC_SMEM);

    int B = in_sizes[0] / 34;        // x is (B,17,2)
    if (B <= 0) return;
    int M17 = B * 17;
    int gF = (B + 7) / 8;
    double invN = 1.0 / ((double)B * 64.0);

    k_zero<<<1, 68>>>();
    k_tr<<<(1088 * 256 + 255) / 256, 256>>>(W_p1, wp1t);
    k_tr2<<<(256 * 128 + 255) / 256, 256>>>(W_p2, wp2t);
    k_trg<<<16, 256>>>(W_gc1, wgt1);
    k_trg<<<16, 256>>>(W_gc2, wgt2);
    // enc + agg + BN1 stats -> y1 (fp16) in bufA
    k_fuse<1><<<gF, 256>>>(x, W_enc, b_enc, bufA, B, 0);
    k_fin<<<1, 32>>>(gamma1, beta1, invN, 0);
    // gc1 (tf32 mma): h2 = relu(bn1(y1) @ W_gc1 + b) -> bufB (fp16)
    k_gc<1><<<M17 / 128, 256, GC_SMEM>>>(bufA, wgt1, b_gc1, bufB, M17);
    // agg(h2) + BN2 stats -> y2 (fp16) in bufA
    k_fuse<0><<<gF, 256>>>(bufB, 0, 0, bufA, B, 1);
    k_fin<<<1, 32>>>(gamma2, beta2, invN, 1);
    // gc2 (tf32 mma): pooled = relu(bn2(y2) @ W_gc2 + b) -> bufB (fp16)
    k_gc<2><<<M17 / 128, 256, GC_SMEM>>>(bufA, wgt2, b_gc2, bufB, M17);
    // p1 (fp16 mma): z = relu(pooled @ W_p1 + b_p1) -> z (fp16)
    k_pmma<1088, 256, 1, 1, 0><<<dim3(2, B / 128), 256, PH_SMEM>>>(bufB, wp1t, b_p1, z);
    // p2 (fp16 mma) + fused L2 normalize -> out (fp32)
    k_pmma<256, 128, 0, 0, 1><<<dim3(1, B / 128), 256, PH_SMEM>>>(z, wp2t, b_p2, out);
}

// round 14
// speedup vs baseline: 1.6009x; 1.0202x over previous
#include <cuda_runtime.h>
#include <cuda_fp16.h>
#include <math.h>
#include <stdint.h>

#define BMAX 65536

// ---- scratch (allocation-free rule: __device__ globals) ----
// bufA/bufB hold node-major activations: plane n at n*B64, element (n,b,c) at n*B64+b*64+c.
__device__ __align__(16) __half g_bufA[(size_t)BMAX * 17 * 64];
__device__ __align__(16) __half g_bufB[(size_t)BMAX * 17 * 64];
__device__ __align__(16) __half g_z[(size_t)BMAX * 256];
__device__ __align__(16) __half g_wp1t[256 * 1088];   // W_p1^T (n-major), fp16
__device__ __align__(16) __half g_wp2t[128 * 256];    // W_p2^T (n-major), fp16
__device__ __align__(16) __half g_wgt1[64 * 64];      // W_gc1^T (n-major), fp16
__device__ __align__(16) __half g_wgt2[64 * 64];      // W_gc2^T (n-major), fp16
__device__ double g_stats[68];
__device__ float g_scale1[17], g_shift1[17], g_scale2[17], g_shift2[17];

// ---- adjacency tables (I + A_norm) ----
__constant__ int   c_cnt[17] = {2,0,0,0,0,4,4,2,2,1,1,3,3,2,2,1,1};
__constant__ float c_w[17]   = {0.5f,0.f,0.f,0.f,0.f,0.25f,0.25f,0.5f,0.5f,1.f,1.f,
                                (1.f/3.f),(1.f/3.f),0.5f,0.5f,1.f,1.f};
__constant__ int   c_nb[17][4] = {
    {5,6,0,0},  {0,0,0,0}, {0,0,0,0}, {0,0,0,0}, {0,0,0,0},
    {7,6,11,0}, {8,5,12,0},
    {5,9,0,0},  {6,10,0,0},
    {7,0,0,0},  {8,0,0,0},
    {5,12,13,0},{6,11,14,0},
    {11,15,0,0},{12,16,0,0},
    {13,0,0,0}, {14,0,0,0}
};

// ---- helpers ----
__device__ __forceinline__ uint32_t s2u(const void* p) {
    uint32_t a;
    asm("{ .reg .u64 t; cvta.to.shared.u64 t, %1; cvt.u32.u64 %0, t; }" : "=r"(a) : "l"(p));
    return a;
}
__device__ __forceinline__ uint32_t lds32(uint32_t addr) {
    uint32_t v;
    asm volatile("ld.shared.b32 %0, [%1];" : "=r"(v) : "r"(addr));
    return v;
}
// XOR swizzle on 16B chunks for 64B rows (k_pmma layout).
__device__ __forceinline__ uint32_t swz(int row, int chunk) {
    return (uint32_t)(row * 64 + ((chunk ^ ((row >> 1) & 3)) << 4));
}
#define MMA_F16(acc, a0, a1, a2, a3, b0, b1) \
    asm volatile( \
        "mma.sync.aligned.m16n8k16.row.col.f32.f16.f16.f32 " \
        "{%0,%1,%2,%3}, {%4,%5,%6,%7}, {%8,%9}, {%0,%1,%2,%3};" \
        : "+f"(acc[0]), "+f"(acc[1]), "+f"(acc[2]), "+f"(acc[3]) \
        : "r"(a0), "r"(a1), "r"(a2), "r"(a3), "r"(b0), "r"(b1))

__global__ void k_zero() {
    if (threadIdx.x < 68) g_stats[threadIdx.x] = 0.0;
}

// ---- transpose W_p1 (1088x256) -> (256x1088), fp16 ----
__global__ void __launch_bounds__(256)
k_tr(const float* __restrict__ W, __half* __restrict__ T) {
    int i = blockIdx.x * 256 + threadIdx.x;
    if (i >= 1088 * 256) return;
    int k = i >> 8, n = i & 255;
    T[(size_t)n * 1088 + k] = __float2half_rn(W[i]);
}

// ---- transpose W_p2 (256x128) -> (128x256), fp16 ----
__global__ void __launch_bounds__(256)
k_tr2(const float* __restrict__ W, __half* __restrict__ T) {
    int i = blockIdx.x * 256 + threadIdx.x;
    if (i >= 256 * 128) return;
    int k = i >> 7, n = i & 127;
    T[(size_t)n * 256 + k] = __float2half_rn(W[i]);
}

// ---- transpose W_gc (64x64) -> (n-major 64x64), fp16 ----
__global__ void __launch_bounds__(256)
k_trg(const float* __restrict__ W, __half* __restrict__ T) {
    int i = blockIdx.x * 256 + threadIdx.x;
    if (i >= 4096) return;
    int k = i >> 6, n = i & 63;
    T[n * 64 + k] = __float2half_rn(W[i]);
}

// ---- stats-only: BN1 stats of y1 = enc(x)+agg from x (sample-major x) ----
__global__ void __launch_bounds__(256)
k_st1(const float* __restrict__ x, const float* __restrict__ W,
      const float* __restrict__ bvec, int B) {
    __shared__ float h_sm[8 * 1156];
    __shared__ float ss[17], qq[17];
    int tid = threadIdx.x;
    int s0 = blockIdx.x * 8;
    if (tid < 17) { ss[tid] = 0.f; qq[tid] = 0.f; }

    for (int idx = tid; idx < 272; idx += 256) {
        int n = idx >> 4, c4 = idx & 15;
        float4 w0 = *(const float4*)(W + c4 * 4);
        float4 w1 = *(const float4*)(W + 64 + c4 * 4);
        float4 bb = *(const float4*)(bvec + c4 * 4);
#pragma unroll
        for (int s = 0; s < 8; s++) {
            int e = s0 + s;
            if (e >= B) break;
            float x0 = x[((size_t)e * 17 + n) * 2];
            float x1 = x[((size_t)e * 17 + n) * 2 + 1];
            float4 v;
            v.x = fmaxf(fmaf(x0, w0.x, fmaf(x1, w1.x, bb.x)), 0.f);
            v.y = fmaxf(fmaf(x0, w0.y, fmaf(x1, w1.y, bb.y)), 0.f);
            v.z = fmaxf(fmaf(x0, w0.z, fmaf(x1, w1.z, bb.z)), 0.f);
            v.w = fmaxf(fmaf(x0, w0.w, fmaf(x1, w1.w, bb.w)), 0.f);
            *(float4*)&h_sm[s * 1156 + n * 68 + c4 * 4] = v;
        }
    }
    __syncthreads();

    for (int idx = tid; idx < 272; idx += 256) {
        int n = idx >> 4, c4 = idx & 15;
        float w = c_w[n];
        int cnt = c_cnt[n];
        float sp = 0.f, qp = 0.f;
#pragma unroll
        for (int s = 0; s < 8; s++) {
            int e = s0 + s;
            if (e >= B) break;
            float4 acc = *(const float4*)&h_sm[s * 1156 + n * 68 + c4 * 4];
            for (int j = 0; j < cnt; j++) {
                const float4 hb = *(const float4*)&h_sm[s * 1156 + c_nb[n][j] * 68 + c4 * 4];
                acc.x = fmaf(w, hb.x, acc.x);
                acc.y = fmaf(w, hb.y, acc.y);
                acc.z = fmaf(w, hb.z, acc.z);
                acc.w = fmaf(w, hb.w, acc.w);
            }
            sp += acc.x + acc.y + acc.z + acc.w;
            qp = fmaf(acc.x, acc.x, fmaf(acc.y, acc.y, fmaf(acc.z, acc.z, fmaf(acc.w, acc.w, qp))));
        }
        atomicAdd(&ss[n], sp);
        atomicAdd(&qq[n], qp);
    }
    __syncthreads();
    if (tid < 17) {
        atomicAdd(&g_stats[2 * tid], (double)ss[tid]);
        atomicAdd(&g_stats[2 * tid + 1], (double)qq[tid]);
    }
}

// ---- stats-only: BN2 stats of y2 = h2+agg(h2), h2 node-major fp16 ----
__global__ void __launch_bounds__(256)
k_st2(const __half* __restrict__ h, int B, size_t B64) {
    __shared__ float h_sm[8 * 1156];
    __shared__ float ss[17], qq[17];
    int tid = threadIdx.x;
    int s0 = blockIdx.x * 8;
    if (tid < 17) { ss[tid] = 0.f; qq[tid] = 0.f; }

    for (int idx = tid; idx < 272; idx += 256) {
        int n = idx >> 4, c4 = idx & 15;
#pragma unroll
        for (int s = 0; s < 8; s++) {
            int e = s0 + s;
            if (e >= B) break;
            const __half2* hp = (const __half2*)(h + (size_t)n * B64 + (size_t)e * 64 + c4 * 4);
            float2 f0 = __half22float2(hp[0]);
            float2 f1 = __half22float2(hp[1]);
            *(float4*)&h_sm[s * 1156 + n * 68 + c4 * 4] = make_float4(f0.x, f0.y, f1.x, f1.y);
        }
    }
    __syncthreads();

    for (int idx = tid; idx < 272; idx += 256) {
        int n = idx >> 4, c4 = idx & 15;
        float w = c_w[n];
        int cnt = c_cnt[n];
        float sp = 0.f, qp = 0.f;
#pragma unroll
        for (int s = 0; s < 8; s++) {
            int e = s0 + s;
            if (e >= B) break;
            float4 acc = *(const float4*)&h_sm[s * 1156 + n * 68 + c4 * 4];
            for (int j = 0; j < cnt; j++) {
                const float4 hb = *(const float4*)&h_sm[s * 1156 + c_nb[n][j] * 68 + c4 * 4];
                acc.x = fmaf(w, hb.x, acc.x);
                acc.y = fmaf(w, hb.y, acc.y);
                acc.z = fmaf(w, hb.z, acc.z);
                acc.w = fmaf(w, hb.w, acc.w);
            }
            sp += acc.x + acc.y + acc.z + acc.w;
            qp = fmaf(acc.x, acc.x, fmaf(acc.y, acc.y, fmaf(acc.z, acc.z, fmaf(acc.w, acc.w, qp))));
        }
        atomicAdd(&ss[n], sp);
        atomicAdd(&qq[n], qp);
    }
    __syncthreads();
    if (tid < 17) {
        atomicAdd(&g_stats[34 + 2 * tid], (double)ss[tid]);
        atomicAdd(&g_stats[34 + 2 * tid + 1], (double)qq[tid]);
    }
}

// ---- finalize BN stats -> fused scale/shift ----
__global__ void k_fin(const float* __restrict__ gamma, const float* __restrict__ beta,
                      double invN, int set) {
    int i = threadIdx.x;
    if (i >= 17) return;
    double s = g_stats[set * 34 + 2 * i];
    double q = g_stats[set * 34 + 2 * i + 1];
    double mean = s * invN;
    double var = q * invN - mean * mean;
    if (var < 0.0) var = 0.0;
    float inv = (float)(1.0 / sqrt(var + 1e-5));
    float sc = gamma[i] * inv;
    float sh = beta[i] - (float)mean * sc;
    if (set == 0) { g_scale1[i] = sc; g_shift1[i] = sh; }
    else          { g_scale2[i] = sc; g_shift2[i] = sh; }
}

// ---- fused gc layer, node-major, fp16 mma ----
// LAYER=1: src = x (float, sample-major (B,17,2)); h = relu(enc(x)).
// LAYER=2: src = h2 (half, node-major planes).
// A-row b = affine(h[node][b] + w*sum h[nb][b]); C = relu(A @ W + bias) -> plane node.
// grid: (17, B/128); block 256. smem: As[128][88] + Ws[64][88] halves (bank-clean stride).
template <int LAYER>
__global__ void __launch_bounds__(256)
k_gc(const void* __restrict__ src, const float* __restrict__ Wenc,
     const float* __restrict__ benc, const __half* __restrict__ Wt,
     const float* __restrict__ bias, __half* __restrict__ C, size_t B64) {
    __shared__ __half As[128 * 88];
    __shared__ __half Ws[64 * 88];
    const int tid = threadIdx.x;
    const int w = tid >> 5, lane = tid & 31;
    const int gid = lane >> 2, tig = lane & 3;
    const int node = blockIdx.x;
    const size_t b0 = (size_t)blockIdx.y * 128;
    const int wm = (w >> 1) * 32, wn = (w & 1) * 32;
    const float sc = (LAYER == 1) ? g_scale1[node] : g_scale2[node];
    const float sh = (LAYER == 1) ? g_shift1[node] : g_shift2[node];
    const int cnt = c_cnt[node];
    const float wgt = c_w[node];

    // Build A: 1024 tasks (row, seg of 8 channels)
#pragma unroll
    for (int it = 0; it < 4; it++) {
        int u = tid + it * 256;
        int row = u >> 3, seg = u & 7;
        size_t b = b0 + row;
        float vals[8];
        if (LAYER == 1) {
            const float* x = (const float*)src;
            float4 w0a = *(const float4*)(Wenc + seg * 8);
            float4 w0b = *(const float4*)(Wenc + seg * 8 + 4);
            float4 w1a = *(const float4*)(Wenc + 64 + seg * 8);
            float4 w1b = *(const float4*)(Wenc + 64 + seg * 8 + 4);
            float4 bea = *(const float4*)(benc + seg * 8);
            float4 beb = *(const float4*)(benc + seg * 8 + 4);
            float2 xp = *(const float2*)(x + (b * 17 + node) * 2);
            vals[0] = fmaxf(fmaf(xp.x, w0a.x, fmaf(xp.y, w1a.x, bea.x)), 0.f);
            vals[1] = fmaxf(fmaf(xp.x, w0a.y, fmaf(xp.y, w1a.y, bea.y)), 0.f);
            vals[2] = fmaxf(fmaf(xp.x, w0a.z, fmaf(xp.y, w1a.z, bea.z)), 0.f);
            vals[3] = fmaxf(fmaf(xp.x, w0a.w, fmaf(xp.y, w1a.w, bea.w)), 0.f);
            vals[4] = fmaxf(fmaf(xp.x, w0b.x, fmaf(xp.y, w1b.x, beb.x)), 0.f);
            vals[5] = fmaxf(fmaf(xp.x, w0b.y, fmaf(xp.y, w1b.y, beb.y)), 0.f);
            vals[6] = fmaxf(fmaf(xp.x, w0b.z, fmaf(xp.y, w1b.z, beb.z)), 0.f);
            vals[7] = fmaxf(fmaf(xp.x, w0b.w, fmaf(xp.y, w1b.w, beb.w)), 0.f);
            for (int j = 0; j < cnt; j++) {
                float2 xn = *(const float2*)(x + (b * 17 + c_nb[node][j]) * 2);
                vals[0] += wgt * fmaxf(fmaf(xn.x, w0a.x, fmaf(xn.y, w1a.x, bea.x)), 0.f);
                vals[1] += wgt * fmaxf(fmaf(xn.x, w0a.y, fmaf(xn.y, w1a.y, bea.y)), 0.f);
                vals[2] += wgt * fmaxf(fmaf(xn.x, w0a.z, fmaf(xn.y, w1a.z, bea.z)), 0.f);
                vals[3] += wgt * fmaxf(fmaf(xn.x, w0a.w, fmaf(xn.y, w1a.w, bea.w)), 0.f);
                vals[4] += wgt * fmaxf(fmaf(xn.x, w0b.x, fmaf(xn.y, w1b.x, beb.x)), 0.f);
                vals[5] += wgt * fmaxf(fmaf(xn.x, w0b.y, fmaf(xn.y, w1b.y, beb.y)), 0.f);
                vals[6] += wgt * fmaxf(fmaf(xn.x, w0b.z, fmaf(xn.y, w1b.z, beb.z)), 0.f);
                vals[7] += wgt * fmaxf(fmaf(xn.x, w0b.w, fmaf(xn.y, w1b.w, beb.w)), 0.f);
            }
        } else {
            const __half* h = (const __half*)src;
            uint4 raw = *(const uint4*)(h + (size_t)node * B64 + b * 64 + seg * 8);
            const __half2* rp = (const __half2*)&raw;
#pragma unroll
            for (int p = 0; p < 4; p++) {
                float2 f = __half22float2(rp[p]);
                vals[2 * p] = f.x; vals[2 * p + 1] = f.y;
            }
            for (int j = 0; j < cnt; j++) {
                uint4 rn = *(const uint4*)(h + (size_t)c_nb[node][j] * B64 + b * 64 + seg * 8);
                const __half2* np = (const __half2*)&rn;
#pragma unroll
                for (int p = 0; p < 4; p++) {
                    float2 f = __half22float2(np[p]);
                    vals[2 * p] = fmaf(wgt, f.x, vals[2 * p]);
                    vals[2 * p + 1] = fmaf(wgt, f.y, vals[2 * p + 1]);
                }
            }
        }
        __half2 hv[4];
#pragma unroll
        for (int p = 0; p < 4; p++)
            hv[p] = __floats2half2_rn(fmaf(vals[2 * p], sc, sh), fmaf(vals[2 * p + 1], sc, sh));
        *(uint4*)&As[row * 88 + seg * 8] = *(uint4*)hv;
    }
    // W tile: 64 rows x 8 segs
#pragma unroll
    for (int it = 0; it < 2; it++) {
        int u = tid + it * 256;
        int row = u >> 3, seg = u & 7;
        *(uint4*)&Ws[row * 88 + seg * 8] = *(const uint4*)(Wt + row * 64 + seg * 8);
    }
    __syncthreads();

    float acc[2][4][4];
#pragma unroll
    for (int mi = 0; mi < 2; mi++)
#pragma unroll
        for (int ni = 0; ni < 4; ni++)
#pragma unroll
            for (int r = 0; r < 4; r++) acc[mi][ni][r] = 0.f;

#pragma unroll
    for (int ks = 0; ks < 4; ks++) {
        uint32_t af[2][4], bf[4][2];
#pragma unroll
        for (int mi = 0; mi < 2; mi++) {
            int rm = wm + mi * 16 + gid;
            af[mi][0] = *(const uint32_t*)&As[rm * 88 + ks * 16 + tig * 2];
            af[mi][1] = *(const uint32_t*)&As[(rm + 8) * 88 + ks * 16 + tig * 2];
            af[mi][2] = *(const uint32_t*)&As[rm * 88 + ks * 16 + 8 + tig * 2];
            af[mi][3] = *(const uint32_t*)&As[(rm + 8) * 88 + ks * 16 + 8 + tig * 2];
        }
#pragma unroll
        for (int ni = 0; ni < 4; ni++) {
            int rn = wn + ni * 8 + gid;
            bf[ni][0] = *(const uint32_t*)&Ws[rn * 88 + ks * 16 + tig * 2];
            bf[ni][1] = *(const uint32_t*)&Ws[rn * 88 + ks * 16 + 8 + tig * 2];
        }
#pragma unroll
        for (int mi = 0; mi < 2; mi++)
#pragma unroll
            for (int ni = 0; ni < 4; ni++)
                MMA_F16(acc[mi][ni], af[mi][0], af[mi][1], af[mi][2], af[mi][3],
                        bf[ni][0], bf[ni][1]);
    }

#pragma unroll
    for (int mi = 0; mi < 2; mi++) {
        size_t row = b0 + wm + mi * 16 + gid;
#pragma unroll
        for (int ni = 0; ni < 4; ni++) {
            int col = wn + ni * 8 + tig * 2;
            float bb0 = __ldg(bias + col), bb1 = __ldg(bias + col + 1);
            float r00 = fmaxf(acc[mi][ni][0] + bb0, 0.f);
            float r01 = fmaxf(acc[mi][ni][1] + bb1, 0.f);
            float r10 = fmaxf(acc[mi][ni][2] + bb0, 0.f);
            float r11 = fmaxf(acc[mi][ni][3] + bb1, 0.f);
            *(__half2*)(C + (size_t)node * B64 + row * 64 + col) = __floats2half2_rn(r00, r01);
            *(__half2*)(C + (size_t)node * B64 + (row + 8) * 64 + col) = __floats2half2_rn(r10, r11);
        }
    }
}

// ---- pool GEMM via fp16 mma (m16n8k16), BM=128, BN=128, double-buffered cp.async ----
// NODEMAJ=1: A rows gathered from node-major planes (k = node*64 + c), arg B64.
#define PH_STAGE 16384
#define PH_SMEM (2 * PH_STAGE)
template <int KDIM, int CN, int RELU, int OUTHALF, int NORM, int NODEMAJ>
__global__ void __launch_bounds__(256)
k_pmma(const __half* __restrict__ A, const __half* __restrict__ Bt,
       const float* __restrict__ bias, void* __restrict__ Cout, size_t B64) {
    extern __shared__ float smf[];
    const uint32_t sb = s2u(smf);
    const int tid = threadIdx.x;
    const int w = tid >> 5, lane = tid & 31;
    const int gid = lane >> 2, tig = lane & 3;
    const size_t m0 = (size_t)blockIdx.y * 128;
    const int n0 = blockIdx.x * 128;
    const int wm = (w >> 2) * 64, wn = (w & 3) * 32;
    const int NCH = KDIM / 32;

    float acc[4][4][4];
#pragma unroll
    for (int mi = 0; mi < 4; mi++)
#pragma unroll
        for (int ni = 0; ni < 4; ni++)
#pragma unroll
            for (int r = 0; r < 4; r++) acc[mi][ni][r] = 0.f;

    auto load_chunk = [&](int c, int s) {
        uint32_t base = sb + (uint32_t)s * PH_STAGE;
        int kc = c * 32;
#pragma unroll
        for (int j = 0; j < 2; j++) {            // A: 128 rows x 4 x 16B
            int u = tid + j * 256;
            int row = u >> 2, cc = u & 3;
            const __half* src;
            if (NODEMAJ) {
                int kk = kc + cc * 8;
                int nd = kk >> 6, ko = kk & 63;
                src = A + (size_t)nd * B64 + (m0 + row) * 64 + ko;
            } else {
                src = A + (m0 + row) * (size_t)KDIM + kc + cc * 8;
            }
            uint32_t d = base + swz(row, cc);
            asm volatile("cp.async.cg.shared.global [%0], [%1], 16;" :: "r"(d), "l"(src) : "memory");
        }
#pragma unroll
        for (int j = 0; j < 2; j++) {            // B: 128 n-rows x 4 x 16B
            int u = tid + j * 256;
            int row = u >> 2, cc = u & 3;
            const __half* src = Bt + (size_t)(n0 + row) * KDIM + kc + cc * 8;
            uint32_t d = base + 8192 + swz(row, cc);
            asm volatile("cp.async.cg.shared.global [%0], [%1], 16;" :: "r"(d), "l"(src) : "memory");
        }
        asm volatile("cp.async.commit_group;" ::: "memory");
    };

    load_chunk(0, 0);
    if (NCH > 1) load_chunk(1, 1);

    for (int c = 0; c < NCH; c++) {
        int s = c & 1;
        if (c == NCH - 1) asm volatile("cp.async.wait_group 0;" ::: "memory");
        else              asm volatile("cp.async.wait_group 1;" ::: "memory");
        __syncthreads();
        uint32_t baseA = sb + (uint32_t)s * PH_STAGE;
        uint32_t baseB = baseA + 8192;
#pragma unroll
        for (int ks = 0; ks < 2; ks++) {
            int c0 = 2 * ks, c1 = 2 * ks + 1;
            uint32_t af[4][4], bf[4][2];
#pragma unroll
            for (int mi = 0; mi < 4; mi++) {
                int r0 = wm + mi * 16 + gid, r1 = r0 + 8;
                af[mi][0] = lds32(baseA + swz(r0, c0) + tig * 4);
                af[mi][1] = lds32(baseA + swz(r1, c0) + tig * 4);
                af[mi][2] = lds32(baseA + swz(r0, c1) + tig * 4);
                af[mi][3] = lds32(baseA + swz(r1, c1) + tig * 4);
            }
#pragma unroll
            for (int ni = 0; ni < 4; ni++) {
                int rn = wn + ni * 8 + gid;
                bf[ni][0] = lds32(baseB + swz(rn, c0) + tig * 4);
                bf[ni][1] = lds32(baseB + swz(rn, c1) + tig * 4);
            }
#pragma unroll
            for (int mi = 0; mi < 4; mi++)
#pragma unroll
                for (int ni = 0; ni < 4; ni++)
                    MMA_F16(acc[mi][ni], af[mi][0], af[mi][1], af[mi][2], af[mi][3],
                            bf[ni][0], bf[ni][1]);
        }
        __syncthreads();
        if (c + 2 < NCH) load_chunk(c + 2, s);
    }

#pragma unroll
    for (int mi = 0; mi < 4; mi++)
#pragma unroll
        for (int ni = 0; ni < 4; ni++) {
            int col = n0 + wn + ni * 8 + tig * 2;
            float b0 = __ldg(bias + col), b1 = __ldg(bias + col + 1);
            acc[mi][ni][0] += b0; acc[mi][ni][1] += b1;
            acc[mi][ni][2] += b0; acc[mi][ni][3] += b1;
            if (RELU) {
#pragma unroll
                for (int r = 0; r < 4; r++) acc[mi][ni][r] = fmaxf(acc[mi][ni][r], 0.f);
            }
        }

    float rs[4][2];
    if (NORM) {
        float* rowssq = smf;
        for (int i = tid; i < 128; i += 256) rowssq[i] = 0.f;
        __syncthreads();
#pragma unroll
        for (int mi = 0; mi < 4; mi++) {
            float p0 = 0.f, p1 = 0.f;
#pragma unroll
            for (int ni = 0; ni < 4; ni++) {
                p0 = fmaf(acc[mi][ni][0], acc[mi][ni][0], fmaf(acc[mi][ni][1], acc[mi][ni][1], p0));
                p1 = fmaf(acc[mi][ni][2], acc[mi][ni][2], fmaf(acc[mi][ni][3], acc[mi][ni][3], p1));
            }
            atomicAdd(&rowssq[wm + mi * 16 + gid], p0);
            atomicAdd(&rowssq[wm + mi * 16 + gid + 8], p1);
        }
        __syncthreads();
#pragma unroll
        for (int mi = 0; mi < 4; mi++) {
            rs[mi][0] = 1.f / fmaxf(sqrtf(rowssq[wm + mi * 16 + gid]), 1e-12f);
            rs[mi][1] = 1.f / fmaxf(sqrtf(rowssq[wm + mi * 16 + gid + 8]), 1e-12f);
        }
    }

#pragma unroll
    for (int mi = 0; mi < 4; mi++) {
        size_t row = m0 + wm + mi * 16 + gid;
#pragma unroll
        for (int ni = 0; ni < 4; ni++) {
            int col = n0 + wn + ni * 8 + tig * 2;
            float v00 = acc[mi][ni][0], v01 = acc[mi][ni][1];
            float v10 = acc[mi][ni][2], v11 = acc[mi][ni][3];
            if (NORM) {
                v00 *= rs[mi][0]; v01 *= rs[mi][0];
                v10 *= rs[mi][1]; v11 *= rs[mi][1];
            }
            if (OUTHALF) {
                __half* Ch = (__half*)Cout;
                *(__half2*)(Ch + row * CN + col) = __floats2half2_rn(v00, v01);
                *(__half2*)(Ch + (row + 8) * CN + col) = __floats2half2_rn(v10, v11);
            } else {
                float* Cf = (float*)Cout;
                *(float2*)(Cf + row * CN + col) = make_float2(v00, v01);
                *(float2*)(Cf + (row + 8) * CN + col) = make_float2(v10, v11);
            }
        }
    }
}

extern "C" void kernel_launch(void* const* d_in, const int* in_sizes, int n_in,
                              void* d_out, int out_size) {
    const float* x      = (const float*)d_in[0];
    const float* W_enc  = (const float*)d_in[1];
    const float* b_enc  = (const float*)d_in[2];
    const float* W_gc1  = (const float*)d_in[3];
    const float* b_gc1  = (const float*)d_in[4];
    const float* W_gc2  = (const float*)d_in[5];
    const float* b_gc2  = (const float*)d_in[6];
    const float* gamma1 = (const float*)d_in[7];
    const float* beta1  = (const float*)d_in[8];
    const float* gamma2 = (const float*)d_in[9];
    const float* beta2  = (const float*)d_in[10];
    const float* W_p1   = (const float*)d_in[11];
    const float* b_p1   = (const float*)d_in[12];
    const float* W_p2   = (const float*)d_in[13];
    const float* b_p2   = (const float*)d_in[14];
    float* out = (float*)d_out;

    // Resolve device addresses of __device__ globals (host shadow != device ptr).
    __half *bufA = 0, *bufB = 0, *z = 0, *wp1t = 0, *wp2t = 0, *wgt1 = 0, *wgt2 = 0;
    cudaGetSymbolAddress((void**)&bufA, g_bufA);
    cudaGetSymbolAddress((void**)&bufB, g_bufB);
    cudaGetSymbolAddress((void**)&z,    g_z);
    cudaGetSymbolAddress((void**)&wp1t, g_wp1t);
    cudaGetSymbolAddress((void**)&wp2t, g_wp2t);
    cudaGetSymbolAddress((void**)&wgt1, g_wgt1);
    cudaGetSymbolAddress((void**)&wgt2, g_wgt2);

    cudaFuncSetAttribute((const void*)k_pmma<1088, 256, 1, 1, 0, 1>,
                         cudaFuncAttributeMaxDynamicSharedMemorySize, PH_SMEM);
    cudaFuncSetAttribute((const void*)k_pmma<256, 128, 0, 0, 1, 0>,
                         cudaFuncAttributeMaxDynamicSharedMemorySize, PH_SMEM);

    int B = in_sizes[0] / 34;        // x is (B,17,2)
    if (B <= 0) return;
    size_t B64 = (size_t)B * 64;
    int gF = (B + 7) / 8;
    double invN = 1.0 / ((double)B * 64.0);

    k_zero<<<1, 68>>>();
    k_tr<<<(1088 * 256 + 255) / 256, 256>>>(W_p1, wp1t);
    k_tr2<<<(256 * 128 + 255) / 256, 256>>>(W_p2, wp2t);
    k_trg<<<16, 256>>>(W_gc1, wgt1);
    k_trg<<<16, 256>>>(W_gc2, wgt2);
    // BN1 stats directly from x (no y1 materialization)
    k_st1<<<gF, 256>>>(x, W_enc, b_enc, B);
    k_fin<<<1, 32>>>(gamma1, beta1, invN, 0);
    // gc1 fused enc+agg+BN1+GEMM -> h2 planes (node-major, fp16) in bufB
    k_gc<1><<<dim3(17, B / 128), 256>>>(x, W_enc, b_enc, wgt1, b_gc1, bufB, B64);
    // BN2 stats from h2 planes
    k_st2<<<gF, 256>>>(bufB, B, B64);
    k_fin<<<1, 32>>>(gamma2, beta2, invN, 1);
    // gc2 fused agg+BN2+GEMM -> pooled planes (node-major, fp16) in bufA
    k_gc<2><<<dim3(17, B / 128), 256>>>(bufB, 0, 0, wgt2, b_gc2, bufA, B64);
    // p1 (fp16 mma, node-major A gather): z = relu(pooled @ W_p1 + b_p1) -> z (B,256)
    k_pmma<1088, 256, 1, 1, 0, 1><<<dim3(2, B / 128), 256, PH_SMEM>>>(bufA, wp1t, b_p1, z, B64);
    // p2 (fp16 mma) + fused L2 normalize -> out (B,128) fp32
    k_pmma<256, 128, 0, 0, 1, 0><<<dim3(1, B / 128), 256, PH_SMEM>>>(z, wp2t, b_p2, out, 0);
}

// round 15
// speedup vs baseline: 1.7531x; 1.0951x over previous
#include <cuda_runtime.h>
#include <cuda_fp16.h>
#include <math.h>
#include <stdint.h>

#define BMAX 65536

// ---- scratch (allocation-free rule: __device__ globals) ----
// bufA/bufB hold node-major activations: plane n at n*B64, element (n,b,c) at n*B64+b*64+c.
__device__ __align__(16) __half g_bufA[(size_t)BMAX * 17 * 64];
__device__ __align__(16) __half g_bufB[(size_t)BMAX * 17 * 64];
__device__ __align__(16) __half g_z[(size_t)BMAX * 256];
__device__ __align__(16) __half g_wp1t[256 * 1088];   // W_p1^T (n-major), fp16
__device__ __align__(16) __half g_wp2t[128 * 256];    // W_p2^T (n-major), fp16
__device__ __align__(16) __half g_wgt1[64 * 64];      // W_gc1^T (n-major), fp16
__device__ __align__(16) __half g_wgt2[64 * 64];      // W_gc2^T (n-major), fp16
__device__ double g_stats[68];
__device__ float g_scale1[17], g_shift1[17], g_scale2[17], g_shift2[17];

// ---- adjacency tables (I + A_norm) ----
__constant__ int   c_cnt[17] = {2,0,0,0,0,4,4,2,2,1,1,3,3,2,2,1,1};
__constant__ float c_w[17]   = {0.5f,0.f,0.f,0.f,0.f,0.25f,0.25f,0.5f,0.5f,1.f,1.f,
                                (1.f/3.f),(1.f/3.f),0.5f,0.5f,1.f,1.f};
__constant__ int   c_nb[17][4] = {
    {5,6,0,0},  {0,0,0,0}, {0,0,0,0}, {0,0,0,0}, {0,0,0,0},
    {7,6,11,0}, {8,5,12,0},
    {5,9,0,0},  {6,10,0,0},
    {7,0,0,0},  {8,0,0,0},
    {5,12,13,0},{6,11,14,0},
    {11,15,0,0},{12,16,0,0},
    {13,0,0,0}, {14,0,0,0}
};

#define STATS_GRID 592

// ---- helpers ----
__device__ __forceinline__ uint32_t s2u(const void* p) {
    uint32_t a;
    asm("{ .reg .u64 t; cvta.to.shared.u64 t, %1; cvt.u32.u64 %0, t; }" : "=r"(a) : "l"(p));
    return a;
}
__device__ __forceinline__ uint32_t lds32(uint32_t addr) {
    uint32_t v;
    asm volatile("ld.shared.b32 %0, [%1];" : "=r"(v) : "r"(addr));
    return v;
}
// XOR swizzle on 16B chunks for 64B rows (k_pmma layout).
__device__ __forceinline__ uint32_t swz(int row, int chunk) {
    return (uint32_t)(row * 64 + ((chunk ^ ((row >> 1) & 3)) << 4));
}
#define MMA_F16(acc, a0, a1, a2, a3, b0, b1) \
    asm volatile( \
        "mma.sync.aligned.m16n8k16.row.col.f32.f16.f16.f32 " \
        "{%0,%1,%2,%3}, {%4,%5,%6,%7}, {%8,%9}, {%0,%1,%2,%3};" \
        : "+f"(acc[0]), "+f"(acc[1]), "+f"(acc[2]), "+f"(acc[3]) \
        : "r"(a0), "r"(a1), "r"(a2), "r"(a3), "r"(b0), "r"(b1))

// ---- merged prep: stats zero + all 4 weight transposes, one launch ----
// blocks [0,1088): W_p1^T; [1088,1216): W_p2^T; [1216,1232): wgt1;
// [1232,1248): wgt2; block 1248: zero stats.
__global__ void __launch_bounds__(256)
k_prep(const float* __restrict__ Wp1, const float* __restrict__ Wp2,
       const float* __restrict__ Wg1, const float* __restrict__ Wg2,
       __half* __restrict__ Tp1, __half* __restrict__ Tp2,
       __half* __restrict__ Tg1, __half* __restrict__ Tg2) {
    int bid = blockIdx.x;
    int tid = threadIdx.x;
    if (bid < 1088) {
        int i = bid * 256 + tid;               // 1088*256 = 278528 = 1088x256 exactly
        int k = i >> 8, n = i & 255;
        Tp1[(size_t)n * 1088 + k] = __float2half_rn(Wp1[i]);
    } else if (bid < 1216) {
        int i = (bid - 1088) * 256 + tid;      // 128*256 = 32768 = 256x128 exactly
        int k = i >> 7, n = i & 127;
        Tp2[(size_t)n * 256 + k] = __float2half_rn(Wp2[i]);
    } else if (bid < 1232) {
        int i = (bid - 1216) * 256 + tid;      // 4096
        int k = i >> 6, n = i & 63;
        Tg1[n * 64 + k] = __float2half_rn(Wg1[i]);
    } else if (bid < 1248) {
        int i = (bid - 1232) * 256 + tid;
        int k = i >> 6, n = i & 63;
        Tg2[n * 64 + k] = __float2half_rn(Wg2[i]);
    } else {
        if (tid < 68) g_stats[tid] = 0.0;
    }
}

// ---- stats, grid-stride + register accumulation ----
// ENC=1: y1 stats from x (float, sample-major); ENC=0: y2 stats from h planes (half).
template <int ENC>
__global__ void __launch_bounds__(256)
k_st(const void* __restrict__ src, const float* __restrict__ W,
     const float* __restrict__ bvec, int B, size_t B64, int set) {
    __shared__ float h_sm[8 * 1156];
    __shared__ float ss[17], qq[17];
    int tid = threadIdx.x;
    if (tid < 17) { ss[tid] = 0.f; qq[tid] = 0.f; }

    // this thread's (up to 2) tasks: idx = tid, and tid+256 if tid<16
    int n0i = tid >> 4, c40 = tid & 15;
    int n1i = (tid + 256) >> 4, c41 = tid & 15;   // only valid for tid<16
    float sp0 = 0.f, qp0 = 0.f, sp1 = 0.f, qp1 = 0.f;

    float4 w00, w10, bb0, w01, w11, bb1;
    if (ENC) {
        w00 = *(const float4*)(W + c40 * 4);
        w10 = *(const float4*)(W + 64 + c40 * 4);
        bb0 = *(const float4*)(bvec + c40 * 4);
        w01 = w00; w11 = w10; bb1 = bb0;   // c41 == c40
    }

    int nG = (B + 7) / 8;
    for (int g = blockIdx.x; g < nG; g += STATS_GRID) {
        int s0 = g * 8;
        // load phase
        for (int idx = tid; idx < 272; idx += 256) {
            int n = idx >> 4, c4 = idx & 15;
            float4 we0, we1, be;
            if (ENC) {
                we0 = *(const float4*)(W + c4 * 4);
                we1 = *(const float4*)(W + 64 + c4 * 4);
                be = *(const float4*)(bvec + c4 * 4);
            }
#pragma unroll
            for (int s = 0; s < 8; s++) {
                int e = s0 + s;
                if (e >= B) break;
                float4 v;
                if (ENC) {
                    const float* xf = (const float*)src;
                    float x0 = xf[((size_t)e * 17 + n) * 2];
                    float x1 = xf[((size_t)e * 17 + n) * 2 + 1];
                    v.x = fmaxf(fmaf(x0, we0.x, fmaf(x1, we1.x, be.x)), 0.f);
                    v.y = fmaxf(fmaf(x0, we0.y, fmaf(x1, we1.y, be.y)), 0.f);
                    v.z = fmaxf(fmaf(x0, we0.z, fmaf(x1, we1.z, be.z)), 0.f);
                    v.w = fmaxf(fmaf(x0, we0.w, fmaf(x1, we1.w, be.w)), 0.f);
                } else {
                    const __half2* hp = (const __half2*)((const __half*)src +
                                         (size_t)n * B64 + (size_t)e * 64 + c4 * 4);
                    float2 f0 = __half22float2(hp[0]);
                    float2 f1 = __half22float2(hp[1]);
                    v = make_float4(f0.x, f0.y, f1.x, f1.y);
                }
                *(float4*)&h_sm[s * 1156 + n * 68 + c4 * 4] = v;
            }
        }
        __syncthreads();
        // compute phase -> register accumulators
        {
            int n = n0i, c4 = c40;
            float w = c_w[n];
            int cnt = c_cnt[n];
#pragma unroll
            for (int s = 0; s < 8; s++) {
                int e = s0 + s;
                if (e >= B) break;
                float4 acc = *(const float4*)&h_sm[s * 1156 + n * 68 + c4 * 4];
                for (int j = 0; j < cnt; j++) {
                    const float4 hb = *(const float4*)&h_sm[s * 1156 + c_nb[n][j] * 68 + c4 * 4];
                    acc.x = fmaf(w, hb.x, acc.x);
                    acc.y = fmaf(w, hb.y, acc.y);
                    acc.z = fmaf(w, hb.z, acc.z);
                    acc.w = fmaf(w, hb.w, acc.w);
                }
                sp0 += acc.x + acc.y + acc.z + acc.w;
                qp0 = fmaf(acc.x, acc.x, fmaf(acc.y, acc.y, fmaf(acc.z, acc.z, fmaf(acc.w, acc.w, qp0))));
            }
        }
        if (tid < 16) {
            int n = n1i, c4 = c41;
            float w = c_w[n];
            int cnt = c_cnt[n];
#pragma unroll
            for (int s = 0; s < 8; s++) {
                int e = s0 + s;
                if (e >= B) break;
                float4 acc = *(const float4*)&h_sm[s * 1156 + n * 68 + c4 * 4];
                for (int j = 0; j < cnt; j++) {
                    const float4 hb = *(const float4*)&h_sm[s * 1156 + c_nb[n][j] * 68 + c4 * 4];
                    acc.x = fmaf(w, hb.x, acc.x);
                    acc.y = fmaf(w, hb.y, acc.y);
                    acc.z = fmaf(w, hb.z, acc.z);
                    acc.w = fmaf(w, hb.w, acc.w);
                }
                sp1 += acc.x + acc.y + acc.z + acc.w;
                qp1 = fmaf(acc.x, acc.x, fmaf(acc.y, acc.y, fmaf(acc.z, acc.z, fmaf(acc.w, acc.w, qp1))));
            }
        }
        __syncthreads();
    }

    // single smem accumulation, then one global double-atomic pass per block
    atomicAdd(&ss[n0i], sp0);
    atomicAdd(&qq[n0i], qp0);
    if (tid < 16) {
        atomicAdd(&ss[n1i], sp1);
        atomicAdd(&qq[n1i], qp1);
    }
    __syncthreads();
    if (tid < 17) {
        atomicAdd(&g_stats[set * 34 + 2 * tid], (double)ss[tid]);
        atomicAdd(&g_stats[set * 34 + 2 * tid + 1], (double)qq[tid]);
    }
}

// ---- finalize BN stats -> fused scale/shift ----
__global__ void k_fin(const float* __restrict__ gamma, const float* __restrict__ beta,
                      double invN, int set) {
    int i = threadIdx.x;
    if (i >= 17) return;
    double s = g_stats[set * 34 + 2 * i];
    double q = g_stats[set * 34 + 2 * i + 1];
    double mean = s * invN;
    double var = q * invN - mean * mean;
    if (var < 0.0) var = 0.0;
    float inv = (float)(1.0 / sqrt(var + 1e-5));
    float sc = gamma[i] * inv;
    float sh = beta[i] - (float)mean * sc;
    if (set == 0) { g_scale1[i] = sc; g_shift1[i] = sh; }
    else          { g_scale2[i] = sc; g_shift2[i] = sh; }
}

// ---- fused gc layer, node-major, fp16 mma (unchanged from R14 winner) ----
template <int LAYER>
__global__ void __launch_bounds__(256)
k_gc(const void* __restrict__ src, const float* __restrict__ Wenc,
     const float* __restrict__ benc, const __half* __restrict__ Wt,
     const float* __restrict__ bias, __half* __restrict__ C, size_t B64) {
    __shared__ __half As[128 * 88];
    __shared__ __half Ws[64 * 88];
    const int tid = threadIdx.x;
    const int w = tid >> 5, lane = tid & 31;
    const int gid = lane >> 2, tig = lane & 3;
    const int node = blockIdx.x;
    const size_t b0 = (size_t)blockIdx.y * 128;
    const int wm = (w >> 1) * 32, wn = (w & 1) * 32;
    const float sc = (LAYER == 1) ? g_scale1[node] : g_scale2[node];
    const float sh = (LAYER == 1) ? g_shift1[node] : g_shift2[node];
    const int cnt = c_cnt[node];
    const float wgt = c_w[node];

#pragma unroll
    for (int it = 0; it < 4; it++) {
        int u = tid + it * 256;
        int row = u >> 3, seg = u & 7;
        size_t b = b0 + row;
        float vals[8];
        if (LAYER == 1) {
            const float* x = (const float*)src;
            float4 w0a = *(const float4*)(Wenc + seg * 8);
            float4 w0b = *(const float4*)(Wenc + seg * 8 + 4);
            float4 w1a = *(const float4*)(Wenc + 64 + seg * 8);
            float4 w1b = *(const float4*)(Wenc + 64 + seg * 8 + 4);
            float4 bea = *(const float4*)(benc + seg * 8);
            float4 beb = *(const float4*)(benc + seg * 8 + 4);
            float2 xp = *(const float2*)(x + (b * 17 + node) * 2);
            vals[0] = fmaxf(fmaf(xp.x, w0a.x, fmaf(xp.y, w1a.x, bea.x)), 0.f);
            vals[1] = fmaxf(fmaf(xp.x, w0a.y, fmaf(xp.y, w1a.y, bea.y)), 0.f);
            vals[2] = fmaxf(fmaf(xp.x, w0a.z, fmaf(xp.y, w1a.z, bea.z)), 0.f);
            vals[3] = fmaxf(fmaf(xp.x, w0a.w, fmaf(xp.y, w1a.w, bea.w)), 0.f);
            vals[4] = fmaxf(fmaf(xp.x, w0b.x, fmaf(xp.y, w1b.x, beb.x)), 0.f);
            vals[5] = fmaxf(fmaf(xp.x, w0b.y, fmaf(xp.y, w1b.y, beb.y)), 0.f);
            vals[6] = fmaxf(fmaf(xp.x, w0b.z, fmaf(xp.y, w1b.z, beb.z)), 0.f);
            vals[7] = fmaxf(fmaf(xp.x, w0b.w, fmaf(xp.y, w1b.w, beb.w)), 0.f);
            for (int j = 0; j < cnt; j++) {
                float2 xn = *(const float2*)(x + (b * 17 + c_nb[node][j]) * 2);
                vals[0] += wgt * fmaxf(fmaf(xn.x, w0a.x, fmaf(xn.y, w1a.x, bea.x)), 0.f);
                vals[1] += wgt * fmaxf(fmaf(xn.x, w0a.y, fmaf(xn.y, w1a.y, bea.y)), 0.f);
                vals[2] += wgt * fmaxf(fmaf(xn.x, w0a.z, fmaf(xn.y, w1a.z, bea.z)), 0.f);
                vals[3] += wgt * fmaxf(fmaf(xn.x, w0a.w, fmaf(xn.y, w1a.w, bea.w)), 0.f);
                vals[4] += wgt * fmaxf(fmaf(xn.x, w0b.x, fmaf(xn.y, w1b.x, beb.x)), 0.f);
                vals[5] += wgt * fmaxf(fmaf(xn.x, w0b.y, fmaf(xn.y, w1b.y, beb.y)), 0.f);
                vals[6] += wgt * fmaxf(fmaf(xn.x, w0b.z, fmaf(xn.y, w1b.z, beb.z)), 0.f);
                vals[7] += wgt * fmaxf(fmaf(xn.x, w0b.w, fmaf(xn.y, w1b.w, beb.w)), 0.f);
            }
        } else {
            const __half* h = (const __half*)src;
            uint4 raw = *(const uint4*)(h + (size_t)node * B64 + b * 64 + seg * 8);
            const __half2* rp = (const __half2*)&raw;
#pragma unroll
            for (int p = 0; p < 4; p++) {
                float2 f = __half22float2(rp[p]);
                vals[2 * p] = f.x; vals[2 * p + 1] = f.y;
            }
            for (int j = 0; j < cnt; j++) {
                uint4 rn = *(const uint4*)(h + (size_t)c_nb[node][j] * B64 + b * 64 + seg * 8);
                const __half2* np = (const __half2*)&rn;
#pragma unroll
                for (int p = 0; p < 4; p++) {
                    float2 f = __half22float2(np[p]);
                    vals[2 * p] = fmaf(wgt, f.x, vals[2 * p]);
                    vals[2 * p + 1] = fmaf(wgt, f.y, vals[2 * p + 1]);
                }
            }
        }
        __half2 hv[4];
#pragma unroll
        for (int p = 0; p < 4; p++)
            hv[p] = __floats2half2_rn(fmaf(vals[2 * p], sc, sh), fmaf(vals[2 * p + 1], sc, sh));
        *(uint4*)&As[row * 88 + seg * 8] = *(uint4*)hv;
    }
#pragma unroll
    for (int it = 0; it < 2; it++) {
        int u = tid + it * 256;
        int row = u >> 3, seg = u & 7;
        *(uint4*)&Ws[row * 88 + seg * 8] = *(const uint4*)(Wt + row * 64 + seg * 8);
    }
    __syncthreads();

    float acc[2][4][4];
#pragma unroll
    for (int mi = 0; mi < 2; mi++)
#pragma unroll
        for (int ni = 0; ni < 4; ni++)
#pragma unroll
            for (int r = 0; r < 4; r++) acc[mi][ni][r] = 0.f;

#pragma unroll
    for (int ks = 0; ks < 4; ks++) {
        uint32_t af[2][4], bf[4][2];
#pragma unroll
        for (int mi = 0; mi < 2; mi++) {
            int rm = wm + mi * 16 + gid;
            af[mi][0] = *(const uint32_t*)&As[rm * 88 + ks * 16 + tig * 2];
            af[mi][1] = *(const uint32_t*)&As[(rm + 8) * 88 + ks * 16 + tig * 2];
            af[mi][2] = *(const uint32_t*)&As[rm * 88 + ks * 16 + 8 + tig * 2];
            af[mi][3] = *(const uint32_t*)&As[(rm + 8) * 88 + ks * 16 + 8 + tig * 2];
        }
#pragma unroll
        for (int ni = 0; ni < 4; ni++) {
            int rn = wn + ni * 8 + gid;
            bf[ni][0] = *(const uint32_t*)&Ws[rn * 88 + ks * 16 + tig * 2];
            bf[ni][1] = *(const uint32_t*)&Ws[rn * 88 + ks * 16 + 8 + tig * 2];
        }
#pragma unroll
        for (int mi = 0; mi < 2; mi++)
#pragma unroll
            for (int ni = 0; ni < 4; ni++)
                MMA_F16(acc[mi][ni], af[mi][0], af[mi][1], af[mi][2], af[mi][3],
                        bf[ni][0], bf[ni][1]);
    }

#pragma unroll
    for (int mi = 0; mi < 2; mi++) {
        size_t row = b0 + wm + mi * 16 + gid;
#pragma unroll
        for (int ni = 0; ni < 4; ni++) {
            int col = wn + ni * 8 + tig * 2;
            float bb0 = __ldg(bias + col), bb1 = __ldg(bias + col + 1);
            float r00 = fmaxf(acc[mi][ni][0] + bb0, 0.f);
            float r01 = fmaxf(acc[mi][ni][1] + bb1, 0.f);
            float r10 = fmaxf(acc[mi][ni][2] + bb0, 0.f);
            float r11 = fmaxf(acc[mi][ni][3] + bb1, 0.f);
            *(__half2*)(C + (size_t)node * B64 + row * 64 + col) = __floats2half2_rn(r00, r01);
            *(__half2*)(C + (size_t)node * B64 + (row + 8) * 64 + col) = __floats2half2_rn(r10, r11);
        }
    }
}

// ---- pool GEMM via fp16 mma (m16n8k16) (unchanged from R14 winner) ----
#define PH_STAGE 16384
#define PH_SMEM (2 * PH_STAGE)
template <int KDIM, int CN, int RELU, int OUTHALF, int NORM, int NODEMAJ>
__global__ void __launch_bounds__(256)
k_pmma(const __half* __restrict__ A, const __half* __restrict__ Bt,
       const float* __restrict__ bias, void* __restrict__ Cout, size_t B64) {
    extern __shared__ float smf[];
    const uint32_t sb = s2u(smf);
    const int tid = threadIdx.x;
    const int w = tid >> 5, lane = tid & 31;
    const int gid = lane >> 2, tig = lane & 3;
    const size_t m0 = (size_t)blockIdx.y * 128;
    const int n0 = blockIdx.x * 128;
    const int wm = (w >> 2) * 64, wn = (w & 3) * 32;
    const int NCH = KDIM / 32;

    float acc[4][4][4];
#pragma unroll
    for (int mi = 0; mi < 4; mi++)
#pragma unroll
        for (int ni = 0; ni < 4; ni++)
#pragma unroll
            for (int r = 0; r < 4; r++) acc[mi][ni][r] = 0.f;

    auto load_chunk = [&](int c, int s) {
        uint32_t base = sb + (uint32_t)s * PH_STAGE;
        int kc = c * 32;
#pragma unroll
        for (int j = 0; j < 2; j++) {
            int u = tid + j * 256;
            int row = u >> 2, cc = u & 3;
            const __half* src;
            if (NODEMAJ) {
                int kk = kc + cc * 8;
                int nd = kk >> 6, ko = kk & 63;
                src = A + (size_t)nd * B64 + (m0 + row) * 64 + ko;
            } else {
                src = A + (m0 + row) * (size_t)KDIM + kc + cc * 8;
            }
            uint32_t d = base + swz(row, cc);
            asm volatile("cp.async.cg.shared.global [%0], [%1], 16;" :: "r"(d), "l"(src) : "memory");
        }
#pragma unroll
        for (int j = 0; j < 2; j++) {
            int u = tid + j * 256;
            int row = u >> 2, cc = u & 3;
            const __half* src = Bt + (size_t)(n0 + row) * KDIM + kc + cc * 8;
            uint32_t d = base + 8192 + swz(row, cc);
            asm volatile("cp.async.cg.shared.global [%0], [%1], 16;" :: "r"(d), "l"(src) : "memory");
        }
        asm volatile("cp.async.commit_group;" ::: "memory");
    };

    load_chunk(0, 0);
    if (NCH > 1) load_chunk(1, 1);

    for (int c = 0; c < NCH; c++) {
        int s = c & 1;
        if (c == NCH - 1) asm volatile("cp.async.wait_group 0;" ::: "memory");
        else              asm volatile("cp.async.wait_group 1;" ::: "memory");
        __syncthreads();
        uint32_t baseA = sb + (uint32_t)s * PH_STAGE;
        uint32_t baseB = baseA + 8192;
#pragma unroll
        for (int ks = 0; ks < 2; ks++) {
            int c0 = 2 * ks, c1 = 2 * ks + 1;
            uint32_t af[4][4], bf[4][2];
#pragma unroll
            for (int mi = 0; mi < 4; mi++) {
                int r0 = wm + mi * 16 + gid, r1 = r0 + 8;
                af[mi][0] = lds32(baseA + swz(r0, c0) + tig * 4);
                af[mi][1] = lds32(baseA + swz(r1, c0) + tig * 4);
                af[mi][2] = lds32(baseA + swz(r0, c1) + tig * 4);
                af[mi][3] = lds32(baseA + swz(r1, c1) + tig * 4);
            }
#pragma unroll
            for (int ni = 0; ni < 4; ni++) {
                int rn = wn + ni * 8 + gid;
                bf[ni][0] = lds32(baseB + swz(rn, c0) + tig * 4);
                bf[ni][1] = lds32(baseB + swz(rn, c1) + tig * 4);
            }
#pragma unroll
            for (int mi = 0; mi < 4; mi++)
#pragma unroll
                for (int ni = 0; ni < 4; ni++)
                    MMA_F16(acc[mi][ni], af[mi][0], af[mi][1], af[mi][2], af[mi][3],
                            bf[ni][0], bf[ni][1]);
        }
        __syncthreads();
        if (c + 2 < NCH) load_chunk(c + 2, s);
    }

#pragma unroll
    for (int mi = 0; mi < 4; mi++)
#pragma unroll
        for (int ni = 0; ni < 4; ni++) {
            int col = n0 + wn + ni * 8 + tig * 2;
            float b0 = __ldg(bias + col), b1 = __ldg(bias + col + 1);
            acc[mi][ni][0] += b0; acc[mi][ni][1] += b1;
            acc[mi][ni][2] += b0; acc[mi][ni][3] += b1;
            if (RELU) {
#pragma unroll
                for (int r = 0; r < 4; r++) acc[mi][ni][r] = fmaxf(acc[mi][ni][r], 0.f);
            }
        }

    float rs[4][2];
    if (NORM) {
        float* rowssq = smf;
        for (int i = tid; i < 128; i += 256) rowssq[i] = 0.f;
        __syncthreads();
#pragma unroll
        for (int mi = 0; mi < 4; mi++) {
            float p0 = 0.f, p1 = 0.f;
#pragma unroll
            for (int ni = 0; ni < 4; ni++) {
                p0 = fmaf(acc[mi][ni][0], acc[mi][ni][0], fmaf(acc[mi][ni][1], acc[mi][ni][1], p0));
                p1 = fmaf(acc[mi][ni][2], acc[mi][ni][2], fmaf(acc[mi][ni][3], acc[mi][ni][3], p1));
            }
            atomicAdd(&rowssq[wm + mi * 16 + gid], p0);
            atomicAdd(&rowssq[wm + mi * 16 + gid + 8], p1);
        }
        __syncthreads();
#pragma unroll
        for (int mi = 0; mi < 4; mi++) {
            rs[mi][0] = 1.f / fmaxf(sqrtf(rowssq[wm + mi * 16 + gid]), 1e-12f);
            rs[mi][1] = 1.f / fmaxf(sqrtf(rowssq[wm + mi * 16 + gid + 8]), 1e-12f);
        }
    }

#pragma unroll
    for (int mi = 0; mi < 4; mi++) {
        size_t row = m0 + wm + mi * 16 + gid;
#pragma unroll
        for (int ni = 0; ni < 4; ni++) {
            int col = n0 + wn + ni * 8 + tig * 2;
            float v00 = acc[mi][ni][0], v01 = acc[mi][ni][1];
            float v10 = acc[mi][ni][2], v11 = acc[mi][ni][3];
            if (NORM) {
                v00 *= rs[mi][0]; v01 *= rs[mi][0];
                v10 *= rs[mi][1]; v11 *= rs[mi][1];
            }
            if (OUTHALF) {
                __half* Ch = (__half*)Cout;
                *(__half2*)(Ch + row * CN + col) = __floats2half2_rn(v00, v01);
                *(__half2*)(Ch + (row + 8) * CN + col) = __floats2half2_rn(v10, v11);
            } else {
                float* Cf = (float*)Cout;
                *(float2*)(Cf + row * CN + col) = make_float2(v00, v01);
                *(float2*)(Cf + (row + 8) * CN + col) = make_float2(v10, v11);
            }
        }
    }
}

extern "C" void kernel_launch(void* const* d_in, const int* in_sizes, int n_in,
                              void* d_out, int out_size) {
    const float* x      = (const float*)d_in[0];
    const float* W_enc  = (const float*)d_in[1];
    const float* b_enc  = (const float*)d_in[2];
    const float* W_gc1  = (const float*)d_in[3];
    const float* b_gc1  = (const float*)d_in[4];
    const float* W_gc2  = (const float*)d_in[5];
    const float* b_gc2  = (const float*)d_in[6];
    const float* gamma1 = (const float*)d_in[7];
    const float* beta1  = (const float*)d_in[8];
    const float* gamma2 = (const float*)d_in[9];
    const float* beta2  = (const float*)d_in[10];
    const float* W_p1   = (const float*)d_in[11];
    const float* b_p1   = (const float*)d_in[12];
    const float* W_p2   = (const float*)d_in[13];
    const float* b_p2   = (const float*)d_in[14];
    float* out = (float*)d_out;

    // Resolve device addresses of __device__ globals (host shadow != device ptr).
    __half *bufA = 0, *bufB = 0, *z = 0, *wp1t = 0, *wp2t = 0, *wgt1 = 0, *wgt2 = 0;
    cudaGetSymbolAddress((void**)&bufA, g_bufA);
    cudaGetSymbolAddress((void**)&bufB, g_bufB);
    cudaGetSymbolAddress((void**)&z,    g_z);
    cudaGetSymbolAddress((void**)&wp1t, g_wp1t);
    cudaGetSymbolAddress((void**)&wp2t, g_wp2t);
    cudaGetSymbolAddress((void**)&wgt1, g_wgt1);
    cudaGetSymbolAddress((void**)&wgt2, g_wgt2);

    cudaFuncSetAttribute((const void*)k_pmma<1088, 256, 1, 1, 0, 1>,
                         cudaFuncAttributeMaxDynamicSharedMemorySize, PH_SMEM);
    cudaFuncSetAttribute((const void*)k_pmma<256, 128, 0, 0, 1, 0>,
                         cudaFuncAttributeMaxDynamicSharedMemorySize, PH_SMEM);

    int B = in_sizes[0] / 34;        // x is (B,17,2)
    if (B <= 0) return;
    size_t B64 = (size_t)B * 64;
    double invN = 1.0 / ((double)B * 64.0);

    // merged prep: stats zero + 4 weight transposes
    k_prep<<<1249, 256>>>(W_p1, W_p2, W_gc1, W_gc2, wp1t, wp2t, wgt1, wgt2);
    // BN1 stats directly from x
    k_st<1><<<STATS_GRID, 256>>>(x, W_enc, b_enc, B, 0, 0);
    k_fin<<<1, 32>>>(gamma1, beta1, invN, 0);
    // gc1 fused enc+agg+BN1+GEMM -> h2 planes (node-major, fp16) in bufB
    k_gc<1><<<dim3(17, B / 128), 256>>>(x, W_enc, b_enc, wgt1, b_gc1, bufB, B64);
    // BN2 stats from h2 planes
    k_st<0><<<STATS_GRID, 256>>>(bufB, 0, 0, B, B64, 1);
    k_fin<<<1, 32>>>(gamma2, beta2, invN, 1);
    // gc2 fused agg+BN2+GEMM -> pooled planes (node-major, fp16) in bufA
    k_gc<2><<<dim3(17, B / 128), 256>>>(bufB, 0, 0, wgt2, b_gc2, bufA, B64);
    // p1 (fp16 mma, node-major A gather): z = relu(pooled @ W_p1 + b_p1) -> z (B,256)
    k_pmma<1088, 256, 1, 1, 0, 1><<<dim3(2, B / 128), 256, PH_SMEM>>>(bufA, wp1t, b_p1, z, B64);
    // p2 (fp16 mma) + fused L2 normalize -> out (B,128) fp32
    k_pmma<256, 128, 0, 0, 1, 0><<<dim3(1, B / 128), 256, PH_SMEM>>>(z, wp2t, b_p2, out, 0);
}